// round 5
// baseline (speedup 1.0000x reference)
#include <cuda_runtime.h>
#include <cuda_bf16.h>
#include <math.h>
#include <stdint.h>

#define B_   8
#define T_   2048
#define DM_  256
#define HID_ 1024
#define ROWS (B_ * T_)   // 16384

// ---------------- scratch (static device globals; no allocation) ----------------
__device__ float g_v   [ROWS * DM_];
__device__ float g_a   [ROWS * DM_];
__device__ float g_actx[ROWS * DM_];
__device__ float g_x   [ROWS * 3 * DM_];
__device__ float g_h   [ROWS * HID_];

// transposed + bf16-split weights: [N, K] K-major
__device__ __nv_bfloat16 g_wvt_h[DM_ * 1024];
__device__ __nv_bfloat16 g_wvt_l[DM_ * 1024];
__device__ __nv_bfloat16 g_wat_h[DM_ * 768];
__device__ __nv_bfloat16 g_wat_l[DM_ * 768];
__device__ __nv_bfloat16 g_w1t_h[HID_ * 768];
__device__ __nv_bfloat16 g_w1t_l[HID_ * 768];

// ------------------------------- helpers ----------------------------------------
__device__ __forceinline__ uint32_t smem_u32(const void* p) {
    uint32_t a;
    asm("{ .reg .u64 t; cvta.to.shared.u64 t, %1; cvt.u32.u64 %0, t; }"
        : "=r"(a) : "l"(p));
    return a;
}

__device__ __forceinline__ uint32_t bf2(float x, float y) {
    __nv_bfloat162 t = __floats2bfloat162_rn(x, y);
    return *(uint32_t*)&t;
}

__device__ __forceinline__ void ldm4(uint32_t r[4], uint32_t addr) {
    asm volatile("ldmatrix.sync.aligned.m8n8.x4.shared.b16 {%0,%1,%2,%3}, [%4];"
        : "=r"(r[0]), "=r"(r[1]), "=r"(r[2]), "=r"(r[3]) : "r"(addr));
}

__device__ __forceinline__ void mma16816(float d[4], const uint32_t a[4],
                                         const uint32_t b0, const uint32_t b1) {
    asm volatile(
        "mma.sync.aligned.m16n8k16.row.col.f32.bf16.bf16.f32 "
        "{%0,%1,%2,%3}, {%4,%5,%6,%7}, {%8,%9}, {%0,%1,%2,%3};"
        : "+f"(d[0]), "+f"(d[1]), "+f"(d[2]), "+f"(d[3])
        : "r"(a[0]), "r"(a[1]), "r"(a[2]), "r"(a[3]), "r"(b0), "r"(b1));
}

// swizzled byte offset within a tile region: rows of 64B (32 bf16), 16B chunks
// rotated by (r>>1)&3 -> conflict-free ldmatrix phases.
__device__ __forceinline__ int swz(int r, int cb) {
    return r * 64 + (cb ^ (((r >> 1) & 3) << 4));
}

// -------------- weight prep: transpose + bf16 hi/lo split: out[N,K] -------------
__global__ void wprep_kernel(const float* __restrict__ W,
                             __nv_bfloat16* __restrict__ oh,
                             __nv_bfloat16* __restrict__ ol, int K, int N)
{
    __shared__ float t[32][33];
    int k0 = blockIdx.y * 32, n0 = blockIdx.x * 32;
    int x = threadIdx.x, y = threadIdx.y;   // 32 x 8
#pragma unroll
    for (int r = 0; r < 32; r += 8)
        t[y + r][x] = W[(size_t)(k0 + y + r) * N + n0 + x];
    __syncthreads();
#pragma unroll
    for (int r = 0; r < 32; r += 8) {
        float v = t[x][y + r];
        __nv_bfloat16 h = __float2bfloat16(v);
        float lo = v - __bfloat162float(h);
        size_t idx = (size_t)(n0 + y + r) * K + k0 + x;
        oh[idx] = h;
        ol[idx] = __float2bfloat16(lo);
    }
}

// ---------------- HMMA GEMM: C = epi(A @ Bt^T + bias), 3-term bf16 --------------
// A [M,K] fp32 row-major (converted on the fly); Bt hi/lo [N,K] bf16 K-major.
// 512 threads / 16 warps, CTA tile 128x256, warp tile 32x64, BK=32, dbl-buffered.
// EPI: 1 = exact GELU; 2 = LayerNorm over N==256 (full row in CTA).
template <int EPI>
__global__ __launch_bounds__(512, 1)
void gemm_mma(const float* __restrict__ A,
              const __nv_bfloat16* __restrict__ Bth,
              const __nv_bfloat16* __restrict__ Btl,
              const float* __restrict__ bias,
              float* __restrict__ C, int N, int K)
{
    extern __shared__ char smem[];
    constexpr int BM = 128, BN = 256;
    constexpr int A_LO  = BM * 64;           // 8192
    constexpr int B_HI  = BM * 128;          // 16384
    constexpr int B_LO  = BM * 128 + BN * 64;// 32768
    constexpr int STAGE = (BM + BN) * 128;   // 49152

    const int tid = threadIdx.x, wid = tid >> 5, lane = tid & 31;
    const int wm = wid & 3, wn = wid >> 2;
    const int row0 = blockIdx.y * BM, col0 = blockIdx.x * BN;

    float acc[2][8][4];
#pragma unroll
    for (int i = 0; i < 2; i++)
#pragma unroll
        for (int j = 0; j < 8; j++)
#pragma unroll
            for (int q = 0; q < 4; q++) acc[i][j][q] = 0.f;

    // ---- staging mappings ----
    const int ar = tid >> 2;              // A row 0..127, 4 threads/row
    const int aq = (tid & 3) * 8;         // 8 fp32 elems each
    const int bn_ = tid >> 1;             // B row 0..255, 2 threads/row
    const int bq  = (tid & 1) * 16;       // 16 bf16 elems each

    float4 sa0, sa1;
    uint4  sbh[2], sbl[2];

    auto ldgA = [&](int k0) {
        const float4* p = (const float4*)(A + (size_t)(row0 + ar) * K + k0 + aq);
        sa0 = p[0]; sa1 = p[1];
    };
    auto ldgB = [&](int k0) {
        const uint4* ph = (const uint4*)(Bth + (size_t)(col0 + bn_) * K + k0 + bq);
        const uint4* pl = (const uint4*)(Btl + (size_t)(col0 + bn_) * K + k0 + bq);
        sbh[0] = ph[0]; sbh[1] = ph[1];
        sbl[0] = pl[0]; sbl[1] = pl[1];
    };
    auto stsAB = [&](int buf) {
        char* base = smem + buf * STAGE;
        {
            float xs[8] = {sa0.x, sa0.y, sa0.z, sa0.w, sa1.x, sa1.y, sa1.z, sa1.w};
            uint32_t h[4], l[4];
#pragma unroll
            for (int q = 0; q < 4; q++) {
                float x0 = xs[2 * q], x1 = xs[2 * q + 1];
                float h0 = __bfloat162float(__float2bfloat16(x0));
                float h1 = __bfloat162float(__float2bfloat16(x1));
                h[q] = bf2(x0, x1);
                l[q] = bf2(x0 - h0, x1 - h1);
            }
            int cb = aq * 2;   // byte col
            *(uint4*)(base + swz(ar, cb))        = make_uint4(h[0], h[1], h[2], h[3]);
            *(uint4*)(base + A_LO + swz(ar, cb)) = make_uint4(l[0], l[1], l[2], l[3]);
        }
#pragma unroll
        for (int i = 0; i < 2; i++) {
            int cb = bq * 2 + i * 16;
            *(uint4*)(base + B_HI + swz(bn_, cb)) = sbh[i];
            *(uint4*)(base + B_LO + swz(bn_, cb)) = sbl[i];
        }
    };

    // ---- mainloop ----
    ldgA(0); ldgB(0); stsAB(0);
    const int nc = K >> 5;
    for (int c = 0; c < nc; c++) {
        __syncthreads();
        if (c + 1 < nc) { ldgA((c + 1) << 5); ldgB((c + 1) << 5); }

        const uint32_t sb = smem_u32(smem + (c & 1) * STAGE);
#pragma unroll
        for (int ks = 0; ks < 2; ks++) {
            const int cb = ks * 32 + ((lane >> 4) << 4);
            uint32_t ah[2][4], al[2][4];
#pragma unroll
            for (int mf = 0; mf < 2; mf++) {
                int r = wm * 32 + mf * 16 + (lane & 15);
                uint32_t ad = sb + swz(r, cb);
                ldm4(ah[mf], ad);
                ldm4(al[mf], ad + A_LO);
            }
#pragma unroll
            for (int nf2 = 0; nf2 < 4; nf2++) {
                int r = wn * 64 + nf2 * 16 + (lane & 15);
                uint32_t ad = sb + B_HI + swz(r, cb);
                uint32_t tb[4], tl[4];
                ldm4(tb, ad);
                ldm4(tl, ad + (B_LO - B_HI));
#pragma unroll
                for (int mf = 0; mf < 2; mf++) {
                    mma16816(acc[mf][2 * nf2],     ah[mf], tb[0], tb[2]);
                    mma16816(acc[mf][2 * nf2],     ah[mf], tl[0], tl[2]);
                    mma16816(acc[mf][2 * nf2],     al[mf], tb[0], tb[2]);
                    mma16816(acc[mf][2 * nf2 + 1], ah[mf], tb[1], tb[3]);
                    mma16816(acc[mf][2 * nf2 + 1], ah[mf], tl[1], tl[3]);
                    mma16816(acc[mf][2 * nf2 + 1], al[mf], tb[1], tb[3]);
                }
            }
        }
        if (c + 1 < nc) stsAB((c + 1) & 1);
    }

    // ------------------------------- epilogue -----------------------------------
    const int r4 = lane >> 2, c2 = (lane & 3) * 2;
    float2 bs[8];
#pragma unroll
    for (int nf = 0; nf < 8; nf++)
        bs[nf] = *(const float2*)&bias[col0 + wn * 64 + nf * 8 + c2];

    float mu[2][2], inv[2][2];
    if (EPI == 2) {   // LayerNorm over 256 cols
        float2* part = (float2*)(smem + 2 * STAGE);  // [BM][4]
#pragma unroll
        for (int mf = 0; mf < 2; mf++)
#pragma unroll
            for (int h = 0; h < 2; h++) {
                float s1 = 0.f, s2 = 0.f;
#pragma unroll
                for (int nf = 0; nf < 8; nf++) {
                    float v0 = acc[mf][nf][2 * h]     + bs[nf].x;
                    float v1 = acc[mf][nf][2 * h + 1] + bs[nf].y;
                    s1 += v0 + v1; s2 += v0 * v0 + v1 * v1;
                }
                s1 += __shfl_xor_sync(0xffffffffu, s1, 1);
                s2 += __shfl_xor_sync(0xffffffffu, s2, 1);
                s1 += __shfl_xor_sync(0xffffffffu, s1, 2);
                s2 += __shfl_xor_sync(0xffffffffu, s2, 2);
                int rt = wm * 32 + mf * 16 + h * 8 + r4;
                if ((lane & 3) == 0) part[rt * 4 + wn] = make_float2(s1, s2);
            }
        __syncthreads();
#pragma unroll
        for (int mf = 0; mf < 2; mf++)
#pragma unroll
            for (int h = 0; h < 2; h++) {
                int rt = wm * 32 + mf * 16 + h * 8 + r4;
                float s1 = 0.f, s2 = 0.f;
#pragma unroll
                for (int w = 0; w < 4; w++) {
                    float2 p = part[rt * 4 + w];
                    s1 += p.x; s2 += p.y;
                }
                float m = s1 * (1.0f / 256.0f);
                float var = s2 * (1.0f / 256.0f) - m * m;
                mu[mf][h] = m;
                inv[mf][h] = rsqrtf(var + 1e-5f);
            }
    }

#pragma unroll
    for (int mf = 0; mf < 2; mf++)
#pragma unroll
        for (int h = 0; h < 2; h++) {
            int row = row0 + wm * 32 + mf * 16 + h * 8 + r4;
#pragma unroll
            for (int nf = 0; nf < 8; nf++) {
                float v0 = acc[mf][nf][2 * h]     + bs[nf].x;
                float v1 = acc[mf][nf][2 * h + 1] + bs[nf].y;
                if (EPI == 1) {
                    v0 = 0.5f * v0 * (1.0f + erff(v0 * 0.70710678118654752f));
                    v1 = 0.5f * v1 * (1.0f + erff(v1 * 0.70710678118654752f));
                }
                if (EPI == 2) {
                    v0 = (v0 - mu[mf][h]) * inv[mf][h];
                    v1 = (v1 - mu[mf][h]) * inv[mf][h];
                }
                int col = col0 + wn * 64 + nf * 8 + c2;
                *(float2*)&C[(size_t)row * N + col] = make_float2(v0, v1);
            }
        }
}

// -------- fused fractional shift + causal window context: g_actx from g_a -------
__global__ void ctx_kernel(const float* __restrict__ theta)
{
    const int t = blockIdx.x;
    const int b = blockIdx.y;
    const int d = threadIdx.x;

    float th    = fminf(fmaxf(theta[0], -12.f), 12.f);
    float delta = 2.0f + 4.0f / (1.0f + expf(-th));
    float dl    = fminf(fmaxf(delta, 0.f), (float)(T_ - 1));
    float nf    = floorf(dl);
    float alpha = dl - nf;
    int   ni    = (int)nf;

    float center = fminf(fmaxf((float)t + delta, 0.f), (float)t);
    int lo = max(0, (int)floorf(center - 5.0f) - 1);
    int hi = min(t, (int)ceilf (center + 5.0f) + 1);

    const float* ab = g_a + (size_t)b * T_ * DM_;
    float sum = 0.f; int cnt = 0;
    for (int tau = lo; tau <= hi; tau++) {
        if (fabsf((float)tau - center) <= 5.0f) {
            cnt++;
            int i0 = min(max(tau - ni, 0), T_ - 1);
            int i1 = min(i0 + 1, T_ - 1);
            sum += (1.0f - alpha) * ab[i0 * DM_ + d] + alpha * ab[i1 * DM_ + d];
        }
    }
    g_actx[((size_t)b * T_ + t) * DM_ + d] = sum / fmaxf((float)cnt, 1e-8f);
}

// -------- build X = [an, vn, an*vn] with L2 normalization (warp per row) --------
__global__ void buildx_kernel()
{
    const int row  = blockIdx.x * 8 + (threadIdx.x >> 5);
    const int lane = threadIdx.x & 31;
    const float* v  = g_v    + (size_t)row * DM_;
    const float* ac = g_actx + (size_t)row * DM_;

    float vv[8], aa[8];
    float sv = 0.f, sa = 0.f;
#pragma unroll
    for (int i = 0; i < 8; i++) {
        vv[i] = v[lane + 32 * i];
        aa[i] = ac[lane + 32 * i];
        sv += vv[i] * vv[i];
        sa += aa[i] * aa[i];
    }
#pragma unroll
    for (int o = 16; o > 0; o >>= 1) {
        sv += __shfl_xor_sync(0xffffffffu, sv, o);
        sa += __shfl_xor_sync(0xffffffffu, sa, o);
    }
    float iv = 1.0f / fmaxf(sqrtf(sv), 1e-8f);
    float ia = 1.0f / fmaxf(sqrtf(sa), 1e-8f);

    float* x = g_x + (size_t)row * (3 * DM_);
#pragma unroll
    for (int i = 0; i < 8; i++) {
        int d = lane + 32 * i;
        float an = aa[i] * ia, vn = vv[i] * iv;
        x[d]           = an;
        x[DM_ + d]     = vn;
        x[2 * DM_ + d] = an * vn;
    }
}

// -------- W2 dot + clip + sigmoid gate + blend: out = g*a_ctx + (1-g)*v --------
__global__ void gate_kernel(const float* __restrict__ W2, const float* __restrict__ b2,
                            float* __restrict__ out)
{
    const int row = blockIdx.x;
    const int tid = threadIdx.x;
    const float* h = g_h + (size_t)row * HID_;

    float p = 0.f;
#pragma unroll
    for (int i = 0; i < 4; i++) p += h[tid + 256 * i] * W2[tid + 256 * i];
#pragma unroll
    for (int o = 16; o > 0; o >>= 1) p += __shfl_xor_sync(0xffffffffu, p, o);

    __shared__ float sp[8];
    __shared__ float sg;
    if ((tid & 31) == 0) sp[tid >> 5] = p;
    __syncthreads();
    if (tid == 0) {
        float s = 0.f;
#pragma unroll
        for (int i = 0; i < 8; i++) s += sp[i];
        float logit = fminf(fmaxf(s + b2[0], -12.f), 12.f);
        float g = 1.0f / (1.0f + expf(-logit));
        sg = fminf(fmaxf(g, 0.05f), 0.95f);
    }
    __syncthreads();
    float g  = sg;
    float ac = g_actx[(size_t)row * DM_ + tid];
    float v  = g_v  [(size_t)row * DM_ + tid];
    out[(size_t)row * DM_ + tid] = g * ac + (1.0f - g) * v;
}

// --------------------------------- launcher ------------------------------------
extern "C" void kernel_launch(void* const* d_in, const int* in_sizes, int n_in,
                              void* d_out, int out_size)
{
    const float* video = (const float*)d_in[0];
    const float* audio = (const float*)d_in[1];
    const float* Wv    = (const float*)d_in[2];
    const float* bv    = (const float*)d_in[3];
    const float* Wa    = (const float*)d_in[4];
    const float* ba    = (const float*)d_in[5];
    const float* theta = (const float*)d_in[6];
    const float* W1    = (const float*)d_in[7];
    const float* b1    = (const float*)d_in[8];
    const float* W2    = (const float*)d_in[9];
    const float* b2    = (const float*)d_in[10];
    float* out = (float*)d_out;

    float *pv, *pa, *px, *ph;
    cudaGetSymbolAddress((void**)&pv, g_v);
    cudaGetSymbolAddress((void**)&pa, g_a);
    cudaGetSymbolAddress((void**)&px, g_x);
    cudaGetSymbolAddress((void**)&ph, g_h);
    __nv_bfloat16 *wvh, *wvl, *wah, *wal, *w1h, *w1l;
    cudaGetSymbolAddress((void**)&wvh, g_wvt_h);
    cudaGetSymbolAddress((void**)&wvl, g_wvt_l);
    cudaGetSymbolAddress((void**)&wah, g_wat_h);
    cudaGetSymbolAddress((void**)&wal, g_wat_l);
    cudaGetSymbolAddress((void**)&w1h, g_w1t_h);
    cudaGetSymbolAddress((void**)&w1l, g_w1t_l);

    const int SMEM = 2 * 49152 + 128 * 4 * 8;   // 102400
    cudaFuncSetAttribute(gemm_mma<1>, cudaFuncAttributeMaxDynamicSharedMemorySize, SMEM);
    cudaFuncSetAttribute(gemm_mma<2>, cudaFuncAttributeMaxDynamicSharedMemorySize, SMEM);

    dim3 wblk(32, 8);
    wprep_kernel<<<dim3(DM_  / 32, 1024 / 32), wblk>>>(Wv, wvh, wvl, 1024, DM_);
    wprep_kernel<<<dim3(DM_  / 32,  768 / 32), wblk>>>(Wa, wah, wal,  768, DM_);
    wprep_kernel<<<dim3(HID_ / 32,  768 / 32), wblk>>>(W1, w1h, w1l,  768, HID_);

    dim3 blk(512);
    // v = LN(video @ Wv + bv)   M=16384 K=1024 N=256
    gemm_mma<2><<<dim3(1, ROWS / 128), blk, SMEM>>>(video, wvh, wvl, bv, pv, DM_, 1024);
    // a = LN(audio @ Wa + ba)   M=16384 K=768  N=256
    gemm_mma<2><<<dim3(1, ROWS / 128), blk, SMEM>>>(audio, wah, wal, ba, pa, DM_, 768);
    // a_ctx
    ctx_kernel<<<dim3(T_, B_), dim3(256)>>>(theta);
    // X = [an, vn, an*vn]
    buildx_kernel<<<ROWS / 8, dim3(256)>>>();
    // H = gelu(X @ W1 + b1)     M=16384 K=768  N=1024
    gemm_mma<1><<<dim3(HID_ / 256, ROWS / 128), blk, SMEM>>>(px, w1h, w1l, b1, ph, HID_, 768);
    // gate + blend
    gate_kernel<<<ROWS, dim3(256)>>>(W2, b2, out);
}

// round 6
// speedup vs baseline: 1.1002x; 1.1002x over previous
#include <cuda_runtime.h>
#include <cuda_bf16.h>
#include <math.h>
#include <stdint.h>

#define B_   8
#define T_   2048
#define DM_  256
#define HID_ 1024
#define ROWS (B_ * T_)   // 16384

// ---------------- scratch (static device globals; no allocation) ----------------
__device__ float g_v   [ROWS * DM_];
__device__ float g_a   [ROWS * DM_];
__device__ float g_actx[ROWS * DM_];
__device__ float g_x   [ROWS * 3 * DM_];
__device__ float g_h   [ROWS * HID_];

// transposed + bf16-split weights: [N, K] K-major
__device__ __nv_bfloat16 g_wvt_h[DM_ * 1024];
__device__ __nv_bfloat16 g_wvt_l[DM_ * 1024];
__device__ __nv_bfloat16 g_wat_h[DM_ * 768];
__device__ __nv_bfloat16 g_wat_l[DM_ * 768];
__device__ __nv_bfloat16 g_w1t_h[HID_ * 768];
__device__ __nv_bfloat16 g_w1t_l[HID_ * 768];

// ------------------------------- helpers ----------------------------------------
__device__ __forceinline__ uint32_t smem_u32(const void* p) {
    uint32_t a;
    asm("{ .reg .u64 t; cvta.to.shared.u64 t, %1; cvt.u32.u64 %0, t; }"
        : "=r"(a) : "l"(p));
    return a;
}

__device__ __forceinline__ uint32_t bf2(float x, float y) {
    __nv_bfloat162 t = __floats2bfloat162_rn(x, y);
    return *(uint32_t*)&t;
}

__device__ __forceinline__ void ldm4(uint32_t r[4], uint32_t addr) {
    asm volatile("ldmatrix.sync.aligned.m8n8.x4.shared.b16 {%0,%1,%2,%3}, [%4];"
        : "=r"(r[0]), "=r"(r[1]), "=r"(r[2]), "=r"(r[3]) : "r"(addr));
}

__device__ __forceinline__ void mma16816(float d[4], const uint32_t a[4],
                                         const uint32_t b0, const uint32_t b1) {
    asm volatile(
        "mma.sync.aligned.m16n8k16.row.col.f32.bf16.bf16.f32 "
        "{%0,%1,%2,%3}, {%4,%5,%6,%7}, {%8,%9}, {%0,%1,%2,%3};"
        : "+f"(d[0]), "+f"(d[1]), "+f"(d[2]), "+f"(d[3])
        : "r"(a[0]), "r"(a[1]), "r"(a[2]), "r"(a[3]), "r"(b0), "r"(b1));
}

__device__ __forceinline__ void cp16(uint32_t dst, const void* src) {
    asm volatile("cp.async.cg.shared.global [%0], [%1], 16;"
                 :: "r"(dst), "l"(src) : "memory");
}
__device__ __forceinline__ void cp_commit() {
    asm volatile("cp.async.commit_group;" ::: "memory");
}
__device__ __forceinline__ void cp_wait0() {
    asm volatile("cp.async.wait_group 0;" ::: "memory");
}

// -------------- weight prep: transpose + bf16 hi/lo split: out[N,K] -------------
__global__ void wprep_kernel(const float* __restrict__ W,
                             __nv_bfloat16* __restrict__ oh,
                             __nv_bfloat16* __restrict__ ol, int K, int N)
{
    __shared__ float t[32][33];
    int k0 = blockIdx.y * 32, n0 = blockIdx.x * 32;
    int x = threadIdx.x, y = threadIdx.y;   // 32 x 8
#pragma unroll
    for (int r = 0; r < 32; r += 8)
        t[y + r][x] = W[(size_t)(k0 + y + r) * N + n0 + x];
    __syncthreads();
#pragma unroll
    for (int r = 0; r < 32; r += 8) {
        float v = t[x][y + r];
        __nv_bfloat16 h = __float2bfloat16(v);
        float lo = v - __bfloat162float(h);
        size_t idx = (size_t)(n0 + y + r) * K + k0 + x;
        oh[idx] = h;
        ol[idx] = __float2bfloat16(lo);
    }
}

// ---------------- HMMA GEMM: C = epi(A @ Bt^T + bias), 3-term bf16 --------------
// 512 thr / 16 warps, CTA tile 128x256, warp tile 32x64, BK=64, double-buffered.
// Smem rows: 64 bf16 = 128B, swizzle: chunk ^= (row&7). cp.async stages B.
// Addresses precomputed; per-ks address = base XOR (ks<<5); stage = +/-STAGE.
// EPI: 1 = exact GELU; 2 = LayerNorm over N==256 (full row in CTA).
template <int EPI>
__global__ __launch_bounds__(512, 1)
void gemm_mma(const float* __restrict__ A,
              const __nv_bfloat16* __restrict__ Bth,
              const __nv_bfloat16* __restrict__ Btl,
              const float* __restrict__ bias,
              float* __restrict__ C, int N, int K)
{
    extern __shared__ char smem[];
    constexpr int BM = 128, BN = 256;
    constexpr int R_ALO = 16384;             // A lo region
    constexpr int R_BHI = 32768;             // B hi region
    constexpr int R_BLO = 65536;             // B lo region
    constexpr int STAGE = 98304;             // per-stage bytes

    const int tid = threadIdx.x, wid = tid >> 5, lane = tid & 31;
    const int wm = wid & 3, wn = wid >> 2;
    const int row0 = blockIdx.y * BM, col0 = blockIdx.x * BN;
    const uint32_t sb = smem_u32(smem);

    float acc[2][8][4];
#pragma unroll
    for (int i = 0; i < 2; i++)
#pragma unroll
        for (int j = 0; j < 8; j++)
#pragma unroll
            for (int q = 0; q < 4; q++) acc[i][j][q] = 0.f;

    // ---------------- precomputed addresses ----------------
    // read (ldmatrix): phase = lane>>4 folded in; in-loop XOR (ks<<5)
    const int ph = lane >> 4;
    uint32_t rdAh[2], rdAl[2], rdBh[4], rdBl[4];
#pragma unroll
    for (int mf = 0; mf < 2; mf++) {
        int r = wm * 32 + mf * 16 + (lane & 15);
        uint32_t o = (uint32_t)(r * 128 + ((ph ^ (r & 7)) << 4));
        rdAh[mf] = sb + o;
        rdAl[mf] = sb + R_ALO + o;
    }
#pragma unroll
    for (int nf2 = 0; nf2 < 4; nf2++) {
        int r = wn * 64 + nf2 * 16 + (lane & 15);
        uint32_t o = (uint32_t)(r * 128 + ((ph ^ (r & 7)) << 4));
        rdBh[nf2] = sb + R_BHI + o;
        rdBl[nf2] = sb + R_BLO + o;
    }

    // write A (STS after convert): row ar, fp32 cols aq*16..; chunks even
    const int ar = tid >> 2;
    const int ac4 = (tid & 3) * 2;           // even chunk index (0,2,4,6)
    uint32_t wrAh = sb + (uint32_t)(ar * 128 + ((ac4 ^ (ar & 7)) << 4));
    uint32_t wrAl = wrAh + R_ALO;

    // write B (cp.async dst): row br, chunk base bc4 (0 or 4); derive j via XOR(j<<4)
    const int br  = tid >> 1;
    const int bc4 = (tid & 1) * 4;
    uint32_t wrBh = sb + R_BHI + (uint32_t)(br * 128 + ((bc4 ^ (br & 7)) << 4));
    uint32_t wrBl = wrBh + (R_BLO - R_BHI);

    // gmem pointers
    const float* pA = A + (size_t)(row0 + ar) * K + (tid & 3) * 16;
    const char* pBh = (const char*)(Bth + (size_t)(col0 + br) * K + bc4 * 8);
    const char* pBl = (const char*)(Btl + (size_t)(col0 + br) * K + bc4 * 8);

    float4 sa[4];
    auto ldgA = [&](int k0) {
        const float4* p = (const float4*)(pA + k0);
        sa[0] = p[0]; sa[1] = p[1]; sa[2] = p[2]; sa[3] = p[3];
    };
    auto stsA = [&]() {
        uint32_t h[8], l[8];
#pragma unroll
        for (int q = 0; q < 8; q++) {
            float x0 = ((const float*)sa)[2 * q], x1 = ((const float*)sa)[2 * q + 1];
            float h0 = __bfloat162float(__float2bfloat16(x0));
            float h1 = __bfloat162float(__float2bfloat16(x1));
            h[q] = bf2(x0, x1);
            l[q] = bf2(x0 - h0, x1 - h1);
        }
        *(uint4*)(size_t)0;  // (never executed path guard removed below)
    };
    (void)stsA;

    auto stsA2 = [&]() {
        uint32_t h[8], l[8];
#pragma unroll
        for (int q = 0; q < 8; q++) {
            float x0 = ((const float*)sa)[2 * q], x1 = ((const float*)sa)[2 * q + 1];
            float h0 = __bfloat162float(__float2bfloat16(x0));
            float h1 = __bfloat162float(__float2bfloat16(x1));
            h[q] = bf2(x0, x1);
            l[q] = bf2(x0 - h0, x1 - h1);
        }
        asm volatile("st.shared.v4.b32 [%0], {%1,%2,%3,%4};"
                     :: "r"(wrAh), "r"(h[0]), "r"(h[1]), "r"(h[2]), "r"(h[3]) : "memory");
        asm volatile("st.shared.v4.b32 [%0], {%1,%2,%3,%4};"
                     :: "r"(wrAh ^ 16u), "r"(h[4]), "r"(h[5]), "r"(h[6]), "r"(h[7]) : "memory");
        asm volatile("st.shared.v4.b32 [%0], {%1,%2,%3,%4};"
                     :: "r"(wrAl), "r"(l[0]), "r"(l[1]), "r"(l[2]), "r"(l[3]) : "memory");
        asm volatile("st.shared.v4.b32 [%0], {%1,%2,%3,%4};"
                     :: "r"(wrAl ^ 16u), "r"(l[4]), "r"(l[5]), "r"(l[6]), "r"(l[7]) : "memory");
    };
    auto issueB = [&](int k0) {
#pragma unroll
        for (int j = 0; j < 4; j++) {
            cp16(wrBh ^ (uint32_t)(j << 4), pBh + (size_t)k0 * 2 + j * 16);
            cp16(wrBl ^ (uint32_t)(j << 4), pBl + (size_t)k0 * 2 + j * 16);
        }
    };

    // ---------------- prologue: fill stage 0 ----------------
    issueB(0);
    cp_commit();
    ldgA(0);
    stsA2();
    cp_wait0();
    __syncthreads();
    wrAh += STAGE; wrAl += STAGE; wrBh += STAGE; wrBl += STAGE;

    // ---------------- mainloop ----------------
    const int nc = K >> 6;
    for (int c = 0; c < nc; c++) {
        const bool more = (c + 1 < nc);
        if (more) { issueB((c + 1) << 6); cp_commit(); ldgA((c + 1) << 6); }

#pragma unroll
        for (int ks = 0; ks < 4; ks++) {
            const uint32_t kx = (uint32_t)(ks << 5);
            uint32_t ah[2][4], al[2][4];
            ldm4(ah[0], rdAh[0] ^ kx);
            ldm4(ah[1], rdAh[1] ^ kx);
            ldm4(al[0], rdAl[0] ^ kx);
            ldm4(al[1], rdAl[1] ^ kx);
#pragma unroll
            for (int nf2 = 0; nf2 < 4; nf2++) {
                uint32_t tb[4], tl[4];
                ldm4(tb, rdBh[nf2] ^ kx);
                ldm4(tl, rdBl[nf2] ^ kx);
#pragma unroll
                for (int mf = 0; mf < 2; mf++) {
                    mma16816(acc[mf][2 * nf2],     ah[mf], tb[0], tb[2]);
                    mma16816(acc[mf][2 * nf2],     ah[mf], tl[0], tl[2]);
                    mma16816(acc[mf][2 * nf2],     al[mf], tb[0], tb[2]);
                    mma16816(acc[mf][2 * nf2 + 1], ah[mf], tb[1], tb[3]);
                    mma16816(acc[mf][2 * nf2 + 1], ah[mf], tl[1], tl[3]);
                    mma16816(acc[mf][2 * nf2 + 1], al[mf], tb[1], tb[3]);
                }
            }
        }

        if (more) {
            stsA2();
            cp_wait0();
            __syncthreads();
            const int d = (c & 1) ? -STAGE : STAGE;
#pragma unroll
            for (int i = 0; i < 2; i++) { rdAh[i] += d; rdAl[i] += d; }
#pragma unroll
            for (int i = 0; i < 4; i++) { rdBh[i] += d; rdBl[i] += d; }
            wrAh -= d; wrAl -= d; wrBh -= d; wrBl -= d;
        }
    }

    // ------------------------------- epilogue -----------------------------------
    __syncthreads();
    const int r4 = lane >> 2, c2 = (lane & 3) * 2;
    float2 bs[8];
#pragma unroll
    for (int nf = 0; nf < 8; nf++)
        bs[nf] = *(const float2*)&bias[col0 + wn * 64 + nf * 8 + c2];

    float mu[2][2], inv[2][2];
    if (EPI == 2) {   // LayerNorm over 256 cols
        float2* part = (float2*)(smem + 2 * STAGE);  // [BM][4]
#pragma unroll
        for (int mf = 0; mf < 2; mf++)
#pragma unroll
            for (int h = 0; h < 2; h++) {
                float s1 = 0.f, s2 = 0.f;
#pragma unroll
                for (int nf = 0; nf < 8; nf++) {
                    float v0 = acc[mf][nf][2 * h]     + bs[nf].x;
                    float v1 = acc[mf][nf][2 * h + 1] + bs[nf].y;
                    s1 += v0 + v1; s2 += v0 * v0 + v1 * v1;
                }
                s1 += __shfl_xor_sync(0xffffffffu, s1, 1);
                s2 += __shfl_xor_sync(0xffffffffu, s2, 1);
                s1 += __shfl_xor_sync(0xffffffffu, s1, 2);
                s2 += __shfl_xor_sync(0xffffffffu, s2, 2);
                int rt = wm * 32 + mf * 16 + h * 8 + r4;
                if ((lane & 3) == 0) part[rt * 4 + wn] = make_float2(s1, s2);
            }
        __syncthreads();
#pragma unroll
        for (int mf = 0; mf < 2; mf++)
#pragma unroll
            for (int h = 0; h < 2; h++) {
                int rt = wm * 32 + mf * 16 + h * 8 + r4;
                float s1 = 0.f, s2 = 0.f;
#pragma unroll
                for (int w = 0; w < 4; w++) {
                    float2 p = part[rt * 4 + w];
                    s1 += p.x; s2 += p.y;
                }
                float m = s1 * (1.0f / 256.0f);
                float var = s2 * (1.0f / 256.0f) - m * m;
                mu[mf][h] = m;
                inv[mf][h] = rsqrtf(var + 1e-5f);
            }
    }

#pragma unroll
    for (int mf = 0; mf < 2; mf++)
#pragma unroll
        for (int h = 0; h < 2; h++) {
            int row = row0 + wm * 32 + mf * 16 + h * 8 + r4;
#pragma unroll
            for (int nf = 0; nf < 8; nf++) {
                float v0 = acc[mf][nf][2 * h]     + bs[nf].x;
                float v1 = acc[mf][nf][2 * h + 1] + bs[nf].y;
                if (EPI == 1) {
                    v0 = 0.5f * v0 * (1.0f + erff(v0 * 0.70710678118654752f));
                    v1 = 0.5f * v1 * (1.0f + erff(v1 * 0.70710678118654752f));
                }
                if (EPI == 2) {
                    v0 = (v0 - mu[mf][h]) * inv[mf][h];
                    v1 = (v1 - mu[mf][h]) * inv[mf][h];
                }
                int col = col0 + wn * 64 + nf * 8 + c2;
                *(float2*)&C[(size_t)row * N + col] = make_float2(v0, v1);
            }
        }
}

// -------- fused fractional shift + causal window context: g_actx from g_a -------
__global__ void ctx_kernel(const float* __restrict__ theta)
{
    const int t = blockIdx.x;
    const int b = blockIdx.y;
    const int d = threadIdx.x;

    float th    = fminf(fmaxf(theta[0], -12.f), 12.f);
    float delta = 2.0f + 4.0f / (1.0f + expf(-th));
    float dl    = fminf(fmaxf(delta, 0.f), (float)(T_ - 1));
    float nf    = floorf(dl);
    float alpha = dl - nf;
    int   ni    = (int)nf;

    float center = fminf(fmaxf((float)t + delta, 0.f), (float)t);
    int lo = max(0, (int)floorf(center - 5.0f) - 1);
    int hi = min(t, (int)ceilf (center + 5.0f) + 1);

    const float* ab = g_a + (size_t)b * T_ * DM_;
    float sum = 0.f; int cnt = 0;
    for (int tau = lo; tau <= hi; tau++) {
        if (fabsf((float)tau - center) <= 5.0f) {
            cnt++;
            int i0 = min(max(tau - ni, 0), T_ - 1);
            int i1 = min(i0 + 1, T_ - 1);
            sum += (1.0f - alpha) * ab[i0 * DM_ + d] + alpha * ab[i1 * DM_ + d];
        }
    }
    g_actx[((size_t)b * T_ + t) * DM_ + d] = sum / fmaxf((float)cnt, 1e-8f);
}

// -------- build X = [an, vn, an*vn] with L2 normalization (warp per row) --------
__global__ void buildx_kernel()
{
    const int row  = blockIdx.x * 8 + (threadIdx.x >> 5);
    const int lane = threadIdx.x & 31;
    const float* v  = g_v    + (size_t)row * DM_;
    const float* ac = g_actx + (size_t)row * DM_;

    float vv[8], aa[8];
    float sv = 0.f, sa = 0.f;
#pragma unroll
    for (int i = 0; i < 8; i++) {
        vv[i] = v[lane + 32 * i];
        aa[i] = ac[lane + 32 * i];
        sv += vv[i] * vv[i];
        sa += aa[i] * aa[i];
    }
#pragma unroll
    for (int o = 16; o > 0; o >>= 1) {
        sv += __shfl_xor_sync(0xffffffffu, sv, o);
        sa += __shfl_xor_sync(0xffffffffu, sa, o);
    }
    float iv = 1.0f / fmaxf(sqrtf(sv), 1e-8f);
    float ia = 1.0f / fmaxf(sqrtf(sa), 1e-8f);

    float* x = g_x + (size_t)row * (3 * DM_);
#pragma unroll
    for (int i = 0; i < 8; i++) {
        int d = lane + 32 * i;
        float an = aa[i] * ia, vn = vv[i] * iv;
        x[d]           = an;
        x[DM_ + d]     = vn;
        x[2 * DM_ + d] = an * vn;
    }
}

// -------- W2 dot + clip + sigmoid gate + blend: out = g*a_ctx + (1-g)*v --------
__global__ void gate_kernel(const float* __restrict__ W2, const float* __restrict__ b2,
                            float* __restrict__ out)
{
    const int row = blockIdx.x;
    const int tid = threadIdx.x;
    const float* h = g_h + (size_t)row * HID_;

    float p = 0.f;
#pragma unroll
    for (int i = 0; i < 4; i++) p += h[tid + 256 * i] * W2[tid + 256 * i];
#pragma unroll
    for (int o = 16; o > 0; o >>= 1) p += __shfl_xor_sync(0xffffffffu, p, o);

    __shared__ float sp[8];
    __shared__ float sg;
    if ((tid & 31) == 0) sp[tid >> 5] = p;
    __syncthreads();
    if (tid == 0) {
        float s = 0.f;
#pragma unroll
        for (int i = 0; i < 8; i++) s += sp[i];
        float logit = fminf(fmaxf(s + b2[0], -12.f), 12.f);
        float g = 1.0f / (1.0f + expf(-logit));
        sg = fminf(fmaxf(g, 0.05f), 0.95f);
    }
    __syncthreads();
    float g  = sg;
    float ac = g_actx[(size_t)row * DM_ + tid];
    float v  = g_v  [(size_t)row * DM_ + tid];
    out[(size_t)row * DM_ + tid] = g * ac + (1.0f - g) * v;
}

// --------------------------------- launcher ------------------------------------
extern "C" void kernel_launch(void* const* d_in, const int* in_sizes, int n_in,
                              void* d_out, int out_size)
{
    const float* video = (const float*)d_in[0];
    const float* audio = (const float*)d_in[1];
    const float* Wv    = (const float*)d_in[2];
    const float* bv    = (const float*)d_in[3];
    const float* Wa    = (const float*)d_in[4];
    const float* ba    = (const float*)d_in[5];
    const float* theta = (const float*)d_in[6];
    const float* W1    = (const float*)d_in[7];
    const float* b1    = (const float*)d_in[8];
    const float* W2    = (const float*)d_in[9];
    const float* b2    = (const float*)d_in[10];
    float* out = (float*)d_out;

    float *pv, *pa, *px, *ph;
    cudaGetSymbolAddress((void**)&pv, g_v);
    cudaGetSymbolAddress((void**)&pa, g_a);
    cudaGetSymbolAddress((void**)&px, g_x);
    cudaGetSymbolAddress((void**)&ph, g_h);
    __nv_bfloat16 *wvh, *wvl, *wah, *wal, *w1h, *w1l;
    cudaGetSymbolAddress((void**)&wvh, g_wvt_h);
    cudaGetSymbolAddress((void**)&wvl, g_wvt_l);
    cudaGetSymbolAddress((void**)&wah, g_wat_h);
    cudaGetSymbolAddress((void**)&wal, g_wat_l);
    cudaGetSymbolAddress((void**)&w1h, g_w1t_h);
    cudaGetSymbolAddress((void**)&w1l, g_w1t_l);

    const int SMEM = 2 * 98304 + 128 * 4 * 8;   // 200704
    cudaFuncSetAttribute(gemm_mma<1>, cudaFuncAttributeMaxDynamicSharedMemorySize, SMEM);
    cudaFuncSetAttribute(gemm_mma<2>, cudaFuncAttributeMaxDynamicSharedMemorySize, SMEM);

    dim3 wblk(32, 8);
    wprep_kernel<<<dim3(DM_  / 32, 1024 / 32), wblk>>>(Wv, wvh, wvl, 1024, DM_);
    wprep_kernel<<<dim3(DM_  / 32,  768 / 32), wblk>>>(Wa, wah, wal,  768, DM_);
    wprep_kernel<<<dim3(HID_ / 32,  768 / 32), wblk>>>(W1, w1h, w1l,  768, HID_);

    dim3 blk(512);
    // v = LN(video @ Wv + bv)   M=16384 K=1024 N=256
    gemm_mma<2><<<dim3(1, ROWS / 128), blk, SMEM>>>(video, wvh, wvl, bv, pv, DM_, 1024);
    // a = LN(audio @ Wa + ba)   M=16384 K=768  N=256
    gemm_mma<2><<<dim3(1, ROWS / 128), blk, SMEM>>>(audio, wah, wal, ba, pa, DM_, 768);
    // a_ctx
    ctx_kernel<<<dim3(T_, B_), dim3(256)>>>(theta);
    // X = [an, vn, an*vn]
    buildx_kernel<<<ROWS / 8, dim3(256)>>>();
    // H = gelu(X @ W1 + b1)     M=16384 K=768  N=1024
    gemm_mma<1><<<dim3(HID_ / 256, ROWS / 128), blk, SMEM>>>(px, w1h, w1l, b1, ph, HID_, 768);
    // gate + blend
    gate_kernel<<<ROWS, dim3(256)>>>(W2, b2, out);
}

// round 7
// speedup vs baseline: 1.1481x; 1.0435x over previous
#include <cuda_runtime.h>
#include <cuda_bf16.h>
#include <math.h>
#include <stdint.h>

#define B_   8
#define T_   2048
#define DM_  256
#define HID_ 1024
#define ROWS (B_ * T_)   // 16384

// ---------------- scratch (static device globals; no allocation) ----------------
__device__ float g_v   [ROWS * DM_];
__device__ float g_a   [ROWS * DM_];
__device__ float g_actx[ROWS * DM_];
__device__ float g_h   [ROWS * HID_];

// bf16 hi/lo split activations
__device__ __nv_bfloat16 g_vid_h[ROWS * 1024];
__device__ __nv_bfloat16 g_vid_l[ROWS * 1024];
__device__ __nv_bfloat16 g_aud_h[ROWS * 768];
__device__ __nv_bfloat16 g_aud_l[ROWS * 768];
__device__ __nv_bfloat16 g_x_h  [ROWS * 768];
__device__ __nv_bfloat16 g_x_l  [ROWS * 768];

// transposed + bf16-split weights: [N, K] K-major
__device__ __nv_bfloat16 g_wvt_h[DM_ * 1024];
__device__ __nv_bfloat16 g_wvt_l[DM_ * 1024];
__device__ __nv_bfloat16 g_wat_h[DM_ * 768];
__device__ __nv_bfloat16 g_wat_l[DM_ * 768];
__device__ __nv_bfloat16 g_w1t_h[HID_ * 768];
__device__ __nv_bfloat16 g_w1t_l[HID_ * 768];

// ------------------------------- helpers ----------------------------------------
__device__ __forceinline__ uint32_t smem_u32(const void* p) {
    uint32_t a;
    asm("{ .reg .u64 t; cvta.to.shared.u64 t, %1; cvt.u32.u64 %0, t; }"
        : "=r"(a) : "l"(p));
    return a;
}

__device__ __forceinline__ uint32_t bf2(float x, float y) {
    __nv_bfloat162 t = __floats2bfloat162_rn(x, y);
    return *(uint32_t*)&t;
}

__device__ __forceinline__ void ldm4(uint32_t r[4], uint32_t addr) {
    asm volatile("ldmatrix.sync.aligned.m8n8.x4.shared.b16 {%0,%1,%2,%3}, [%4];"
        : "=r"(r[0]), "=r"(r[1]), "=r"(r[2]), "=r"(r[3]) : "r"(addr));
}

__device__ __forceinline__ void mma16816(float d[4], const uint32_t a[4],
                                         const uint32_t b0, const uint32_t b1) {
    asm volatile(
        "mma.sync.aligned.m16n8k16.row.col.f32.bf16.bf16.f32 "
        "{%0,%1,%2,%3}, {%4,%5,%6,%7}, {%8,%9}, {%0,%1,%2,%3};"
        : "+f"(d[0]), "+f"(d[1]), "+f"(d[2]), "+f"(d[3])
        : "r"(a[0]), "r"(a[1]), "r"(a[2]), "r"(a[3]), "r"(b0), "r"(b1));
}

__device__ __forceinline__ void cp16(uint32_t dst, const void* src) {
    asm volatile("cp.async.cg.shared.global [%0], [%1], 16;"
                 :: "r"(dst), "l"(src) : "memory");
}
__device__ __forceinline__ void cp_commit() {
    asm volatile("cp.async.commit_group;" ::: "memory");
}
__device__ __forceinline__ void cp_wait0() {
    asm volatile("cp.async.wait_group 0;" ::: "memory");
}

// -------------- weight prep: transpose + bf16 hi/lo split: out[N,K] -------------
__global__ void wprep_kernel(const float* __restrict__ W,
                             __nv_bfloat16* __restrict__ oh,
                             __nv_bfloat16* __restrict__ ol, int K, int N)
{
    __shared__ float t[32][33];
    int k0 = blockIdx.y * 32, n0 = blockIdx.x * 32;
    int x = threadIdx.x, y = threadIdx.y;   // 32 x 8
#pragma unroll
    for (int r = 0; r < 32; r += 8)
        t[y + r][x] = W[(size_t)(k0 + y + r) * N + n0 + x];
    __syncthreads();
#pragma unroll
    for (int r = 0; r < 32; r += 8) {
        float v = t[x][y + r];
        __nv_bfloat16 h = __float2bfloat16(v);
        float lo = v - __bfloat162float(h);
        size_t idx = (size_t)(n0 + y + r) * K + k0 + x;
        oh[idx] = h;
        ol[idx] = __float2bfloat16(lo);
    }
}

// -------------- activation prep: elementwise bf16 hi/lo split -------------------
__global__ void aprep_kernel(const float* __restrict__ in,
                             __nv_bfloat16* __restrict__ oh,
                             __nv_bfloat16* __restrict__ ol)
{
    size_t i = ((size_t)blockIdx.x * 256 + threadIdx.x) * 4;
    float4 v = *(const float4*)(in + i);
    float hx = __bfloat162float(__float2bfloat16(v.x));
    float hy = __bfloat162float(__float2bfloat16(v.y));
    float hz = __bfloat162float(__float2bfloat16(v.z));
    float hw = __bfloat162float(__float2bfloat16(v.w));
    *(uint2*)(oh + i) = make_uint2(bf2(v.x, v.y), bf2(v.z, v.w));
    *(uint2*)(ol + i) = make_uint2(bf2(v.x - hx, v.y - hy), bf2(v.z - hz, v.w - hw));
}

// ---------------- HMMA GEMM: C = epi(A @ Bt^T + bias), 3-term bf16 --------------
// A hi/lo [M,K] bf16 row-major; Bt hi/lo [N,K] bf16 K-major. Pure cp.async
// mainloop (no LDG/CVT/STS). 512 thr / 16 warps, tile 128x256, warp 32x64,
// BK=64 (128B rows, XOR-8 swizzle), double-buffered smem.
// EPI: 1 = exact GELU; 2 = LayerNorm over N==256 (full row in CTA).
template <int EPI>
__global__ __launch_bounds__(512, 1)
void gemm_mma(const __nv_bfloat16* __restrict__ Ah,
              const __nv_bfloat16* __restrict__ Al,
              const __nv_bfloat16* __restrict__ Bth,
              const __nv_bfloat16* __restrict__ Btl,
              const float* __restrict__ bias,
              float* __restrict__ C, int N, int K)
{
    extern __shared__ char smem[];
    constexpr int BM = 128, BN = 256;
    constexpr int R_ALO = 16384;
    constexpr int R_BHI = 32768;
    constexpr int R_BLO = 65536;
    constexpr int STAGE = 98304;

    const int tid = threadIdx.x, wid = tid >> 5, lane = tid & 31;
    const int wm = wid & 3, wn = wid >> 2;
    const int row0 = blockIdx.y * BM, col0 = blockIdx.x * BN;
    const uint32_t sb = smem_u32(smem);

    float acc[2][8][4];
#pragma unroll
    for (int i = 0; i < 2; i++)
#pragma unroll
        for (int j = 0; j < 8; j++)
#pragma unroll
            for (int q = 0; q < 4; q++) acc[i][j][q] = 0.f;

    // ---------------- precomputed addresses ----------------
    const int ph = lane >> 4;
    uint32_t rdAh[2], rdAl[2], rdBh[4], rdBl[4];
#pragma unroll
    for (int mf = 0; mf < 2; mf++) {
        int r = wm * 32 + mf * 16 + (lane & 15);
        uint32_t o = (uint32_t)(r * 128 + ((ph ^ (r & 7)) << 4));
        rdAh[mf] = sb + o;
        rdAl[mf] = sb + R_ALO + o;
    }
#pragma unroll
    for (int nf2 = 0; nf2 < 4; nf2++) {
        int r = wn * 64 + nf2 * 16 + (lane & 15);
        uint32_t o = (uint32_t)(r * 128 + ((ph ^ (r & 7)) << 4));
        rdBh[nf2] = sb + R_BHI + o;
        rdBl[nf2] = sb + R_BLO + o;
    }

    // cp.async destinations
    const int ar  = tid >> 2;             // A row, 4 thr/row
    const int ac0 = (tid & 3) * 2;        // chunk pair base (even)
    uint32_t wrAh = sb + (uint32_t)(ar * 128 + ((ac0 ^ (ar & 7)) << 4));
    uint32_t wrAl = wrAh + R_ALO;
    const int br  = tid >> 1;             // B row, 2 thr/row
    const int bc0 = (tid & 1) * 4;        // chunk quad base
    uint32_t wrBh = sb + R_BHI + (uint32_t)(br * 128 + ((bc0 ^ (br & 7)) << 4));
    uint32_t wrBl = wrBh + (R_BLO - R_BHI);

    // gmem byte pointers (advance by 2*k bytes per chunk)
    const char* pAh = (const char*)(Ah + (size_t)(row0 + ar) * K + ac0 * 8);
    const char* pAl = (const char*)(Al + (size_t)(row0 + ar) * K + ac0 * 8);
    const char* pBh = (const char*)(Bth + (size_t)(col0 + br) * K + bc0 * 8);
    const char* pBl = (const char*)(Btl + (size_t)(col0 + br) * K + bc0 * 8);

    auto issue = [&](int k0) {
        size_t off = (size_t)k0 * 2;
        cp16(wrAh,        pAh + off);
        cp16(wrAh ^ 16u,  pAh + off + 16);
        cp16(wrAl,        pAl + off);
        cp16(wrAl ^ 16u,  pAl + off + 16);
#pragma unroll
        for (int j = 0; j < 4; j++) {
            cp16(wrBh ^ (uint32_t)(j << 4), pBh + off + j * 16);
            cp16(wrBl ^ (uint32_t)(j << 4), pBl + off + j * 16);
        }
    };

    // ---------------- prologue: fill stage 0 ----------------
    issue(0);
    cp_commit();
    cp_wait0();
    __syncthreads();
    wrAh += STAGE; wrAl += STAGE; wrBh += STAGE; wrBl += STAGE;

    // ---------------- mainloop ----------------
    const int nc = K >> 6;
    for (int c = 0; c < nc; c++) {
        const bool more = (c + 1 < nc);
        if (more) { issue((c + 1) << 6); cp_commit(); }

#pragma unroll
        for (int ks = 0; ks < 4; ks++) {
            const uint32_t kx = (uint32_t)(ks << 5);
            uint32_t ah[2][4], al[2][4];
            ldm4(ah[0], rdAh[0] ^ kx);
            ldm4(ah[1], rdAh[1] ^ kx);
            ldm4(al[0], rdAl[0] ^ kx);
            ldm4(al[1], rdAl[1] ^ kx);
#pragma unroll
            for (int nf2 = 0; nf2 < 4; nf2++) {
                uint32_t tb[4], tl[4];
                ldm4(tb, rdBh[nf2] ^ kx);
                ldm4(tl, rdBl[nf2] ^ kx);
#pragma unroll
                for (int mf = 0; mf < 2; mf++) {
                    mma16816(acc[mf][2 * nf2],     ah[mf], tb[0], tb[2]);
                    mma16816(acc[mf][2 * nf2],     ah[mf], tl[0], tl[2]);
                    mma16816(acc[mf][2 * nf2],     al[mf], tb[0], tb[2]);
                    mma16816(acc[mf][2 * nf2 + 1], ah[mf], tb[1], tb[3]);
                    mma16816(acc[mf][2 * nf2 + 1], ah[mf], tl[1], tl[3]);
                    mma16816(acc[mf][2 * nf2 + 1], al[mf], tb[1], tb[3]);
                }
            }
        }

        if (more) {
            cp_wait0();
            __syncthreads();
            const int d = (c & 1) ? -STAGE : STAGE;
#pragma unroll
            for (int i = 0; i < 2; i++) { rdAh[i] += d; rdAl[i] += d; }
#pragma unroll
            for (int i = 0; i < 4; i++) { rdBh[i] += d; rdBl[i] += d; }
            wrAh -= d; wrAl -= d; wrBh -= d; wrBl -= d;
        }
    }

    // ------------------------------- epilogue -----------------------------------
    __syncthreads();
    const int r4 = lane >> 2, c2 = (lane & 3) * 2;
    float2 bs[8];
#pragma unroll
    for (int nf = 0; nf < 8; nf++)
        bs[nf] = *(const float2*)&bias[col0 + wn * 64 + nf * 8 + c2];

    float mu[2][2], inv[2][2];
    if (EPI == 2) {   // LayerNorm over 256 cols
        float2* part = (float2*)(smem + 2 * STAGE);  // [BM][4]
#pragma unroll
        for (int mf = 0; mf < 2; mf++)
#pragma unroll
            for (int h = 0; h < 2; h++) {
                float s1 = 0.f, s2 = 0.f;
#pragma unroll
                for (int nf = 0; nf < 8; nf++) {
                    float v0 = acc[mf][nf][2 * h]     + bs[nf].x;
                    float v1 = acc[mf][nf][2 * h + 1] + bs[nf].y;
                    s1 += v0 + v1; s2 += v0 * v0 + v1 * v1;
                }
                s1 += __shfl_xor_sync(0xffffffffu, s1, 1);
                s2 += __shfl_xor_sync(0xffffffffu, s2, 1);
                s1 += __shfl_xor_sync(0xffffffffu, s1, 2);
                s2 += __shfl_xor_sync(0xffffffffu, s2, 2);
                int rt = wm * 32 + mf * 16 + h * 8 + r4;
                if ((lane & 3) == 0) part[rt * 4 + wn] = make_float2(s1, s2);
            }
        __syncthreads();
#pragma unroll
        for (int mf = 0; mf < 2; mf++)
#pragma unroll
            for (int h = 0; h < 2; h++) {
                int rt = wm * 32 + mf * 16 + h * 8 + r4;
                float s1 = 0.f, s2 = 0.f;
#pragma unroll
                for (int w = 0; w < 4; w++) {
                    float2 p = part[rt * 4 + w];
                    s1 += p.x; s2 += p.y;
                }
                float m = s1 * (1.0f / 256.0f);
                float var = s2 * (1.0f / 256.0f) - m * m;
                mu[mf][h] = m;
                inv[mf][h] = rsqrtf(var + 1e-5f);
            }
    }

#pragma unroll
    for (int mf = 0; mf < 2; mf++)
#pragma unroll
        for (int h = 0; h < 2; h++) {
            int row = row0 + wm * 32 + mf * 16 + h * 8 + r4;
#pragma unroll
            for (int nf = 0; nf < 8; nf++) {
                float v0 = acc[mf][nf][2 * h]     + bs[nf].x;
                float v1 = acc[mf][nf][2 * h + 1] + bs[nf].y;
                if (EPI == 1) {
                    v0 = 0.5f * v0 * (1.0f + erff(v0 * 0.70710678118654752f));
                    v1 = 0.5f * v1 * (1.0f + erff(v1 * 0.70710678118654752f));
                }
                if (EPI == 2) {
                    v0 = (v0 - mu[mf][h]) * inv[mf][h];
                    v1 = (v1 - mu[mf][h]) * inv[mf][h];
                }
                int col = col0 + wn * 64 + nf * 8 + c2;
                *(float2*)&C[(size_t)row * N + col] = make_float2(v0, v1);
            }
        }
}

// -------- fused fractional shift + causal window context: g_actx from g_a -------
__global__ void ctx_kernel(const float* __restrict__ theta)
{
    const int t = blockIdx.x;
    const int b = blockIdx.y;
    const int d = threadIdx.x;

    float th    = fminf(fmaxf(theta[0], -12.f), 12.f);
    float delta = 2.0f + 4.0f / (1.0f + expf(-th));
    float dl    = fminf(fmaxf(delta, 0.f), (float)(T_ - 1));
    float nf    = floorf(dl);
    float alpha = dl - nf;
    int   ni    = (int)nf;

    float center = fminf(fmaxf((float)t + delta, 0.f), (float)t);
    int lo = max(0, (int)floorf(center - 5.0f) - 1);
    int hi = min(t, (int)ceilf (center + 5.0f) + 1);

    const float* ab = g_a + (size_t)b * T_ * DM_;
    float sum = 0.f; int cnt = 0;
    for (int tau = lo; tau <= hi; tau++) {
        if (fabsf((float)tau - center) <= 5.0f) {
            cnt++;
            int i0 = min(max(tau - ni, 0), T_ - 1);
            int i1 = min(i0 + 1, T_ - 1);
            sum += (1.0f - alpha) * ab[i0 * DM_ + d] + alpha * ab[i1 * DM_ + d];
        }
    }
    g_actx[((size_t)b * T_ + t) * DM_ + d] = sum / fmaxf((float)cnt, 1e-8f);
}

// -------- build X = [an, vn, an*vn] bf16 hi/lo with L2 norm (warp per row) ------
__global__ void buildx_kernel()
{
    const int row  = blockIdx.x * 8 + (threadIdx.x >> 5);
    const int lane = threadIdx.x & 31;
    const float* v  = g_v    + (size_t)row * DM_;
    const float* ac = g_actx + (size_t)row * DM_;

    float vv[8], aa[8];
    float sv = 0.f, sa = 0.f;
#pragma unroll
    for (int i = 0; i < 8; i++) {
        vv[i] = v[lane + 32 * i];
        aa[i] = ac[lane + 32 * i];
        sv += vv[i] * vv[i];
        sa += aa[i] * aa[i];
    }
#pragma unroll
    for (int o = 16; o > 0; o >>= 1) {
        sv += __shfl_xor_sync(0xffffffffu, sv, o);
        sa += __shfl_xor_sync(0xffffffffu, sa, o);
    }
    float iv = 1.0f / fmaxf(sqrtf(sv), 1e-8f);
    float ia = 1.0f / fmaxf(sqrtf(sa), 1e-8f);

    __nv_bfloat16* xh = g_x_h + (size_t)row * (3 * DM_);
    __nv_bfloat16* xl = g_x_l + (size_t)row * (3 * DM_);
#pragma unroll
    for (int i = 0; i < 8; i++) {
        int d = lane + 32 * i;
        float an = aa[i] * ia, vn = vv[i] * iv, pr = an * vn;
        float hn = __bfloat162float(__float2bfloat16(an));
        float hv = __bfloat162float(__float2bfloat16(vn));
        float hp = __bfloat162float(__float2bfloat16(pr));
        xh[d]            = __float2bfloat16(an);
        xl[d]            = __float2bfloat16(an - hn);
        xh[DM_ + d]      = __float2bfloat16(vn);
        xl[DM_ + d]      = __float2bfloat16(vn - hv);
        xh[2 * DM_ + d]  = __float2bfloat16(pr);
        xl[2 * DM_ + d]  = __float2bfloat16(pr - hp);
    }
}

// -------- W2 dot + clip + sigmoid gate + blend: out = g*a_ctx + (1-g)*v --------
__global__ void gate_kernel(const float* __restrict__ W2, const float* __restrict__ b2,
                            float* __restrict__ out)
{
    const int row = blockIdx.x;
    const int tid = threadIdx.x;
    const float* h = g_h + (size_t)row * HID_;

    float p = 0.f;
#pragma unroll
    for (int i = 0; i < 4; i++) p += h[tid + 256 * i] * W2[tid + 256 * i];
#pragma unroll
    for (int o = 16; o > 0; o >>= 1) p += __shfl_xor_sync(0xffffffffu, p, o);

    __shared__ float sp[8];
    __shared__ float sg;
    if ((tid & 31) == 0) sp[tid >> 5] = p;
    __syncthreads();
    if (tid == 0) {
        float s = 0.f;
#pragma unroll
        for (int i = 0; i < 8; i++) s += sp[i];
        float logit = fminf(fmaxf(s + b2[0], -12.f), 12.f);
        float g = 1.0f / (1.0f + expf(-logit));
        sg = fminf(fmaxf(g, 0.05f), 0.95f);
    }
    __syncthreads();
    float g  = sg;
    float ac = g_actx[(size_t)row * DM_ + tid];
    float v  = g_v  [(size_t)row * DM_ + tid];
    out[(size_t)row * DM_ + tid] = g * ac + (1.0f - g) * v;
}

// --------------------------------- launcher ------------------------------------
extern "C" void kernel_launch(void* const* d_in, const int* in_sizes, int n_in,
                              void* d_out, int out_size)
{
    const float* video = (const float*)d_in[0];
    const float* audio = (const float*)d_in[1];
    const float* Wv    = (const float*)d_in[2];
    const float* bv    = (const float*)d_in[3];
    const float* Wa    = (const float*)d_in[4];
    const float* ba    = (const float*)d_in[5];
    const float* theta = (const float*)d_in[6];
    const float* W1    = (const float*)d_in[7];
    const float* b1    = (const float*)d_in[8];
    const float* W2    = (const float*)d_in[9];
    const float* b2    = (const float*)d_in[10];
    float* out = (float*)d_out;

    float *pv, *pa, *ph;
    cudaGetSymbolAddress((void**)&pv, g_v);
    cudaGetSymbolAddress((void**)&pa, g_a);
    cudaGetSymbolAddress((void**)&ph, g_h);
    __nv_bfloat16 *vidh, *vidl, *audh, *audl, *xh, *xl;
    cudaGetSymbolAddress((void**)&vidh, g_vid_h);
    cudaGetSymbolAddress((void**)&vidl, g_vid_l);
    cudaGetSymbolAddress((void**)&audh, g_aud_h);
    cudaGetSymbolAddress((void**)&audl, g_aud_l);
    cudaGetSymbolAddress((void**)&xh,   g_x_h);
    cudaGetSymbolAddress((void**)&xl,   g_x_l);
    __nv_bfloat16 *wvh, *wvl, *wah, *wal, *w1h, *w1l;
    cudaGetSymbolAddress((void**)&wvh, g_wvt_h);
    cudaGetSymbolAddress((void**)&wvl, g_wvt_l);
    cudaGetSymbolAddress((void**)&wah, g_wat_h);
    cudaGetSymbolAddress((void**)&wal, g_wat_l);
    cudaGetSymbolAddress((void**)&w1h, g_w1t_h);
    cudaGetSymbolAddress((void**)&w1l, g_w1t_l);

    const int SMEM = 2 * 98304 + 128 * 4 * 8;   // 200704
    cudaFuncSetAttribute(gemm_mma<1>, cudaFuncAttributeMaxDynamicSharedMemorySize, SMEM);
    cudaFuncSetAttribute(gemm_mma<2>, cudaFuncAttributeMaxDynamicSharedMemorySize, SMEM);

    dim3 wblk(32, 8);
    wprep_kernel<<<dim3(DM_  / 32, 1024 / 32), wblk>>>(Wv, wvh, wvl, 1024, DM_);
    wprep_kernel<<<dim3(DM_  / 32,  768 / 32), wblk>>>(Wa, wah, wal,  768, DM_);
    wprep_kernel<<<dim3(HID_ / 32,  768 / 32), wblk>>>(W1, w1h, w1l,  768, HID_);
    aprep_kernel<<<(ROWS * 1024) / 1024, 256>>>(video, vidh, vidl);
    aprep_kernel<<<(ROWS * 768)  / 1024, 256>>>(audio, audh, audl);

    dim3 blk(512);
    // v = LN(video @ Wv + bv)   M=16384 K=1024 N=256
    gemm_mma<2><<<dim3(1, ROWS / 128), blk, SMEM>>>(vidh, vidl, wvh, wvl, bv, pv, DM_, 1024);
    // a = LN(audio @ Wa + ba)   M=16384 K=768  N=256
    gemm_mma<2><<<dim3(1, ROWS / 128), blk, SMEM>>>(audh, audl, wah, wal, ba, pa, DM_, 768);
    // a_ctx
    ctx_kernel<<<dim3(T_, B_), dim3(256)>>>(theta);
    // X = [an, vn, an*vn] -> bf16 hi/lo
    buildx_kernel<<<ROWS / 8, dim3(256)>>>();
    // H = gelu(X @ W1 + b1)     M=16384 K=768  N=1024
    gemm_mma<1><<<dim3(HID_ / 256, ROWS / 128), blk, SMEM>>>(xh, xl, w1h, w1l, b1, ph, HID_, 768);
    // gate + blend
    gate_kernel<<<ROWS, dim3(256)>>>(W2, b2, out);
}

// round 8
// speedup vs baseline: 1.4882x; 1.2963x over previous
#include <cuda_runtime.h>
#include <cuda_bf16.h>
#include <math.h>
#include <stdint.h>

#define B_   8
#define T_   2048
#define DM_  256
#define HID_ 1024
#define ROWS (B_ * T_)   // 16384

// ---------------- scratch (static device globals; no allocation) ----------------
__device__ float g_v   [ROWS * DM_];
__device__ float g_a   [ROWS * DM_];
__device__ float g_actx[ROWS * DM_];
__device__ float g_x   [ROWS * 3 * DM_];
__device__ float g_h   [ROWS * HID_];

// transposed weights, tf32-rounded fp32: [N, K] K-major
__device__ float g_wvt[DM_ * 1024];
__device__ float g_wat[DM_ * 768];
__device__ float g_w1t[HID_ * 768];

// ------------------------------- helpers ----------------------------------------
__device__ __forceinline__ uint32_t smem_u32(const void* p) {
    uint32_t a;
    asm("{ .reg .u64 t; cvta.to.shared.u64 t, %1; cvt.u32.u64 %0, t; }"
        : "=r"(a) : "l"(p));
    return a;
}

__device__ __forceinline__ void ldm4(uint32_t r[4], uint32_t addr) {
    asm volatile("ldmatrix.sync.aligned.m8n8.x4.shared.b16 {%0,%1,%2,%3}, [%4];"
        : "=r"(r[0]), "=r"(r[1]), "=r"(r[2]), "=r"(r[3]) : "r"(addr));
}

__device__ __forceinline__ void mma_tf32(float d[4], const uint32_t a[4],
                                         const uint32_t b0, const uint32_t b1) {
    asm volatile(
        "mma.sync.aligned.m16n8k8.row.col.f32.tf32.tf32.f32 "
        "{%0,%1,%2,%3}, {%4,%5,%6,%7}, {%8,%9}, {%0,%1,%2,%3};"
        : "+f"(d[0]), "+f"(d[1]), "+f"(d[2]), "+f"(d[3])
        : "r"(a[0]), "r"(a[1]), "r"(a[2]), "r"(a[3]), "r"(b0), "r"(b1));
}

__device__ __forceinline__ void cvt_tf32(uint32_t& r) {
    asm("cvt.rna.tf32.f32 %0, %0;" : "+r"(r));
}

__device__ __forceinline__ void cp16(uint32_t dst, const void* src) {
    asm volatile("cp.async.cg.shared.global [%0], [%1], 16;"
                 :: "r"(dst), "l"(src) : "memory");
}
__device__ __forceinline__ void cp_commit() {
    asm volatile("cp.async.commit_group;" ::: "memory");
}
__device__ __forceinline__ void cp_wait0() {
    asm volatile("cp.async.wait_group 0;" ::: "memory");
}

// ------ weight prep: transpose + tf32 round: out[N,K] (fp32 storage) ------------
__global__ void wprep_kernel(const float* __restrict__ W,
                             float* __restrict__ ot, int K, int N)
{
    __shared__ float t[32][33];
    int k0 = blockIdx.y * 32, n0 = blockIdx.x * 32;
    int x = threadIdx.x, y = threadIdx.y;   // 32 x 8
#pragma unroll
    for (int r = 0; r < 32; r += 8)
        t[y + r][x] = W[(size_t)(k0 + y + r) * N + n0 + x];
    __syncthreads();
#pragma unroll
    for (int r = 0; r < 32; r += 8) {
        uint32_t u = __float_as_uint(t[x][y + r]);
        cvt_tf32(u);
        ot[(size_t)(n0 + y + r) * K + k0 + x] = __uint_as_float(u);
    }
}

// ------------- TF32 HMMA GEMM: C = epi(A @ Bt^T + bias), single pass ------------
// A [M,K] fp32 row-major (rounded to tf32 in-kernel); Bt [N,K] tf32 K-major.
// 512 thr / 16 warps, CTA tile 128x256, warp tile 32x64, BK=32 (128B rows,
// XOR-8 swizzle), double-buffered, pure cp.async staging.
// EPI: 1 = exact GELU; 2 = LayerNorm over N==256 (full row in CTA).
template <int EPI>
__global__ __launch_bounds__(512, 1)
void gemm_mma(const float* __restrict__ A,
              const float* __restrict__ Bt,
              const float* __restrict__ bias,
              float* __restrict__ C, int N, int K)
{
    extern __shared__ char smem[];
    constexpr int BM = 128, BN = 256;
    constexpr int R_B   = 16384;             // B region offset (A: 128 rows x 128B)
    constexpr int STAGE = 49152;             // (128 + 256) * 128

    const int tid = threadIdx.x, wid = tid >> 5, lane = tid & 31;
    const int wm = wid & 3, wn = wid >> 2;
    const int row0 = blockIdx.y * BM, col0 = blockIdx.x * BN;
    const uint32_t sb = smem_u32(smem);

    float acc[2][8][4];
#pragma unroll
    for (int i = 0; i < 2; i++)
#pragma unroll
        for (int j = 0; j < 8; j++)
#pragma unroll
            for (int q = 0; q < 4; q++) acc[i][j][q] = 0.f;

    // ---------------- precomputed ldmatrix addresses ----------------
    // chunk index = 2*ks + (lane>=16); in-loop XOR (ks<<5)
    const int ph = lane >> 4;
    uint32_t rdA[2], rdB[4];
#pragma unroll
    for (int mf = 0; mf < 2; mf++) {
        int r = wm * 32 + mf * 16 + (lane & 15);
        rdA[mf] = sb + (uint32_t)(r * 128 + ((ph ^ (r & 7)) << 4));
    }
#pragma unroll
    for (int nf2 = 0; nf2 < 4; nf2++) {
        int r = wn * 64 + nf2 * 16 + (lane & 15);
        rdB[nf2] = sb + R_B + (uint32_t)(r * 128 + ((ph ^ (r & 7)) << 4));
    }

    // cp.async destinations
    const int ar  = tid >> 2;             // A row, 4 thr/row (32B each)
    const int ac0 = (tid & 3) * 2;        // even chunk base
    uint32_t wrA = sb + (uint32_t)(ar * 128 + ((ac0 ^ (ar & 7)) << 4));
    const int br  = tid >> 1;             // B row, 2 thr/row (64B each)
    const int bc0 = (tid & 1) * 4;        // chunk quad base
    uint32_t wrB = sb + R_B + (uint32_t)(br * 128 + ((bc0 ^ (br & 7)) << 4));

    // gmem byte pointers (fp32: chunk k0 -> byte offset 4*k0)
    const char* pA = (const char*)(A + (size_t)(row0 + ar) * K + ac0 * 4);
    const char* pB = (const char*)(Bt + (size_t)(col0 + br) * K + bc0 * 4);

    auto issue = [&](int k0) {
        size_t off = (size_t)k0 * 4;
        cp16(wrA,       pA + off);
        cp16(wrA ^ 16u, pA + off + 16);
#pragma unroll
        for (int j = 0; j < 4; j++)
            cp16(wrB ^ (uint32_t)(j << 4), pB + off + j * 16);
    };

    // ---------------- prologue ----------------
    issue(0);
    cp_commit();
    cp_wait0();
    __syncthreads();
    wrA += STAGE; wrB += STAGE;

    // ---------------- mainloop: BK=32, 4 k8-steps per chunk ----------------
    const int nc = K >> 5;
    for (int c = 0; c < nc; c++) {
        const bool more = (c + 1 < nc);
        if (more) { issue((c + 1) << 5); cp_commit(); }

#pragma unroll
        for (int ks = 0; ks < 4; ks++) {
            const uint32_t kx = (uint32_t)(ks << 5);
            uint32_t a[2][4];
            ldm4(a[0], rdA[0] ^ kx);
            ldm4(a[1], rdA[1] ^ kx);
#pragma unroll
            for (int mf = 0; mf < 2; mf++)
#pragma unroll
                for (int q = 0; q < 4; q++) cvt_tf32(a[mf][q]);
#pragma unroll
            for (int nf2 = 0; nf2 < 4; nf2++) {
                uint32_t t[4];
                ldm4(t, rdB[nf2] ^ kx);
#pragma unroll
                for (int mf = 0; mf < 2; mf++) {
                    mma_tf32(acc[mf][2 * nf2],     a[mf], t[0], t[2]);
                    mma_tf32(acc[mf][2 * nf2 + 1], a[mf], t[1], t[3]);
                }
            }
        }

        if (more) {
            cp_wait0();
            __syncthreads();
            const int d = (c & 1) ? -STAGE : STAGE;
            rdA[0] += d; rdA[1] += d;
#pragma unroll
            for (int i = 0; i < 4; i++) rdB[i] += d;
            wrA -= d; wrB -= d;
        }
    }

    // ------------------------------- epilogue -----------------------------------
    __syncthreads();
    const int r4 = lane >> 2, c2 = (lane & 3) * 2;
    float2 bs[8];
#pragma unroll
    for (int nf = 0; nf < 8; nf++)
        bs[nf] = *(const float2*)&bias[col0 + wn * 64 + nf * 8 + c2];

    float mu[2][2], inv[2][2];
    if (EPI == 2) {   // LayerNorm over 256 cols
        float2* part = (float2*)(smem + 2 * STAGE);  // [BM][4]
#pragma unroll
        for (int mf = 0; mf < 2; mf++)
#pragma unroll
            for (int h = 0; h < 2; h++) {
                float s1 = 0.f, s2 = 0.f;
#pragma unroll
                for (int nf = 0; nf < 8; nf++) {
                    float v0 = acc[mf][nf][2 * h]     + bs[nf].x;
                    float v1 = acc[mf][nf][2 * h + 1] + bs[nf].y;
                    s1 += v0 + v1; s2 += v0 * v0 + v1 * v1;
                }
                s1 += __shfl_xor_sync(0xffffffffu, s1, 1);
                s2 += __shfl_xor_sync(0xffffffffu, s2, 1);
                s1 += __shfl_xor_sync(0xffffffffu, s1, 2);
                s2 += __shfl_xor_sync(0xffffffffu, s2, 2);
                int rt = wm * 32 + mf * 16 + h * 8 + r4;
                if ((lane & 3) == 0) part[rt * 4 + wn] = make_float2(s1, s2);
            }
        __syncthreads();
#pragma unroll
        for (int mf = 0; mf < 2; mf++)
#pragma unroll
            for (int h = 0; h < 2; h++) {
                int rt = wm * 32 + mf * 16 + h * 8 + r4;
                float s1 = 0.f, s2 = 0.f;
#pragma unroll
                for (int w = 0; w < 4; w++) {
                    float2 p = part[rt * 4 + w];
                    s1 += p.x; s2 += p.y;
                }
                float m = s1 * (1.0f / 256.0f);
                float var = s2 * (1.0f / 256.0f) - m * m;
                mu[mf][h] = m;
                inv[mf][h] = rsqrtf(var + 1e-5f);
            }
    }

#pragma unroll
    for (int mf = 0; mf < 2; mf++)
#pragma unroll
        for (int h = 0; h < 2; h++) {
            int row = row0 + wm * 32 + mf * 16 + h * 8 + r4;
#pragma unroll
            for (int nf = 0; nf < 8; nf++) {
                float v0 = acc[mf][nf][2 * h]     + bs[nf].x;
                float v1 = acc[mf][nf][2 * h + 1] + bs[nf].y;
                if (EPI == 1) {
                    v0 = 0.5f * v0 * (1.0f + erff(v0 * 0.70710678118654752f));
                    v1 = 0.5f * v1 * (1.0f + erff(v1 * 0.70710678118654752f));
                }
                if (EPI == 2) {
                    v0 = (v0 - mu[mf][h]) * inv[mf][h];
                    v1 = (v1 - mu[mf][h]) * inv[mf][h];
                }
                int col = col0 + wn * 64 + nf * 8 + c2;
                *(float2*)&C[(size_t)row * N + col] = make_float2(v0, v1);
            }
        }
}

// -------- fused fractional shift + causal window context: g_actx from g_a -------
__global__ void ctx_kernel(const float* __restrict__ theta)
{
    const int t = blockIdx.x;
    const int b = blockIdx.y;
    const int d = threadIdx.x;

    float th    = fminf(fmaxf(theta[0], -12.f), 12.f);
    float delta = 2.0f + 4.0f / (1.0f + expf(-th));
    float dl    = fminf(fmaxf(delta, 0.f), (float)(T_ - 1));
    float nf    = floorf(dl);
    float alpha = dl - nf;
    int   ni    = (int)nf;

    float center = fminf(fmaxf((float)t + delta, 0.f), (float)t);
    int lo = max(0, (int)floorf(center - 5.0f) - 1);
    int hi = min(t, (int)ceilf (center + 5.0f) + 1);

    const float* ab = g_a + (size_t)b * T_ * DM_;
    float sum = 0.f; int cnt = 0;
    for (int tau = lo; tau <= hi; tau++) {
        if (fabsf((float)tau - center) <= 5.0f) {
            cnt++;
            int i0 = min(max(tau - ni, 0), T_ - 1);
            int i1 = min(i0 + 1, T_ - 1);
            sum += (1.0f - alpha) * ab[i0 * DM_ + d] + alpha * ab[i1 * DM_ + d];
        }
    }
    g_actx[((size_t)b * T_ + t) * DM_ + d] = sum / fmaxf((float)cnt, 1e-8f);
}

// -------- build X = [an, vn, an*vn] with L2 normalization (warp per row) --------
__global__ void buildx_kernel()
{
    const int row  = blockIdx.x * 8 + (threadIdx.x >> 5);
    const int lane = threadIdx.x & 31;
    const float* v  = g_v    + (size_t)row * DM_;
    const float* ac = g_actx + (size_t)row * DM_;

    float vv[8], aa[8];
    float sv = 0.f, sa = 0.f;
#pragma unroll
    for (int i = 0; i < 8; i++) {
        vv[i] = v[lane + 32 * i];
        aa[i] = ac[lane + 32 * i];
        sv += vv[i] * vv[i];
        sa += aa[i] * aa[i];
    }
#pragma unroll
    for (int o = 16; o > 0; o >>= 1) {
        sv += __shfl_xor_sync(0xffffffffu, sv, o);
        sa += __shfl_xor_sync(0xffffffffu, sa, o);
    }
    float iv = 1.0f / fmaxf(sqrtf(sv), 1e-8f);
    float ia = 1.0f / fmaxf(sqrtf(sa), 1e-8f);

    float* x = g_x + (size_t)row * (3 * DM_);
#pragma unroll
    for (int i = 0; i < 8; i++) {
        int d = lane + 32 * i;
        float an = aa[i] * ia, vn = vv[i] * iv;
        x[d]           = an;
        x[DM_ + d]     = vn;
        x[2 * DM_ + d] = an * vn;
    }
}

// -------- W2 dot + clip + sigmoid gate + blend: out = g*a_ctx + (1-g)*v --------
__global__ void gate_kernel(const float* __restrict__ W2, const float* __restrict__ b2,
                            float* __restrict__ out)
{
    const int row = blockIdx.x;
    const int tid = threadIdx.x;
    const float* h = g_h + (size_t)row * HID_;

    float p = 0.f;
#pragma unroll
    for (int i = 0; i < 4; i++) p += h[tid + 256 * i] * W2[tid + 256 * i];
#pragma unroll
    for (int o = 16; o > 0; o >>= 1) p += __shfl_xor_sync(0xffffffffu, p, o);

    __shared__ float sp[8];
    __shared__ float sg;
    if ((tid & 31) == 0) sp[tid >> 5] = p;
    __syncthreads();
    if (tid == 0) {
        float s = 0.f;
#pragma unroll
        for (int i = 0; i < 8; i++) s += sp[i];
        float logit = fminf(fmaxf(s + b2[0], -12.f), 12.f);
        float g = 1.0f / (1.0f + expf(-logit));
        sg = fminf(fmaxf(g, 0.05f), 0.95f);
    }
    __syncthreads();
    float g  = sg;
    float ac = g_actx[(size_t)row * DM_ + tid];
    float v  = g_v  [(size_t)row * DM_ + tid];
    out[(size_t)row * DM_ + tid] = g * ac + (1.0f - g) * v;
}

// --------------------------------- launcher ------------------------------------
extern "C" void kernel_launch(void* const* d_in, const int* in_sizes, int n_in,
                              void* d_out, int out_size)
{
    const float* video = (const float*)d_in[0];
    const float* audio = (const float*)d_in[1];
    const float* Wv    = (const float*)d_in[2];
    const float* bv    = (const float*)d_in[3];
    const float* Wa    = (const float*)d_in[4];
    const float* ba    = (const float*)d_in[5];
    const float* theta = (const float*)d_in[6];
    const float* W1    = (const float*)d_in[7];
    const float* b1    = (const float*)d_in[8];
    const float* W2    = (const float*)d_in[9];
    const float* b2    = (const float*)d_in[10];
    float* out = (float*)d_out;

    float *pv, *pa, *px, *ph, *wvt, *wat, *w1t;
    cudaGetSymbolAddress((void**)&pv,  g_v);
    cudaGetSymbolAddress((void**)&pa,  g_a);
    cudaGetSymbolAddress((void**)&px,  g_x);
    cudaGetSymbolAddress((void**)&ph,  g_h);
    cudaGetSymbolAddress((void**)&wvt, g_wvt);
    cudaGetSymbolAddress((void**)&wat, g_wat);
    cudaGetSymbolAddress((void**)&w1t, g_w1t);

    const int SMEM = 2 * 49152 + 128 * 4 * 8;   // 102400
    cudaFuncSetAttribute(gemm_mma<1>, cudaFuncAttributeMaxDynamicSharedMemorySize, SMEM);
    cudaFuncSetAttribute(gemm_mma<2>, cudaFuncAttributeMaxDynamicSharedMemorySize, SMEM);

    dim3 wblk(32, 8);
    wprep_kernel<<<dim3(DM_  / 32, 1024 / 32), wblk>>>(Wv, wvt, 1024, DM_);
    wprep_kernel<<<dim3(DM_  / 32,  768 / 32), wblk>>>(Wa, wat,  768, DM_);
    wprep_kernel<<<dim3(HID_ / 32,  768 / 32), wblk>>>(W1, w1t,  768, HID_);

    dim3 blk(512);
    // v = LN(video @ Wv + bv)   M=16384 K=1024 N=256
    gemm_mma<2><<<dim3(1, ROWS / 128), blk, SMEM>>>(video, wvt, bv, pv, DM_, 1024);
    // a = LN(audio @ Wa + ba)   M=16384 K=768  N=256
    gemm_mma<2><<<dim3(1, ROWS / 128), blk, SMEM>>>(audio, wat, ba, pa, DM_, 768);
    // a_ctx
    ctx_kernel<<<dim3(T_, B_), dim3(256)>>>(theta);
    // X = [an, vn, an*vn]
    buildx_kernel<<<ROWS / 8, dim3(256)>>>();
    // H = gelu(X @ W1 + b1)     M=16384 K=768  N=1024
    gemm_mma<1><<<dim3(HID_ / 256, ROWS / 128), blk, SMEM>>>(px, w1t, b1, ph, HID_, 768);
    // gate + blend
    gate_kernel<<<ROWS, dim3(256)>>>(W2, b2, out);
}

// round 9
// speedup vs baseline: 1.5594x; 1.0478x over previous
#include <cuda_runtime.h>
#include <cuda_bf16.h>
#include <math.h>
#include <stdint.h>

#define B_   8
#define T_   2048
#define DM_  256
#define HID_ 1024
#define ROWS (B_ * T_)   // 16384

// ---------------- scratch (static device globals; no allocation) ----------------
__device__ float g_v   [ROWS * DM_];
__device__ float g_a   [ROWS * DM_];
__device__ float g_actx[ROWS * DM_];
__device__ float g_x   [ROWS * 3 * DM_];   // tf32-rounded
__device__ float g_logit[ROWS];

// transposed weights, tf32-rounded fp32: [N, K] K-major
__device__ float g_wvt[DM_ * 1024];
__device__ float g_wat[DM_ * 768];
__device__ float g_w1t[HID_ * 768];

// ------------------------------- helpers ----------------------------------------
__device__ __forceinline__ uint32_t smem_u32(const void* p) {
    uint32_t a;
    asm("{ .reg .u64 t; cvta.to.shared.u64 t, %1; cvt.u32.u64 %0, t; }"
        : "=r"(a) : "l"(p));
    return a;
}

__device__ __forceinline__ void ldm4(uint32_t r[4], uint32_t addr) {
    asm volatile("ldmatrix.sync.aligned.m8n8.x4.shared.b16 {%0,%1,%2,%3}, [%4];"
        : "=r"(r[0]), "=r"(r[1]), "=r"(r[2]), "=r"(r[3]) : "r"(addr));
}

__device__ __forceinline__ void mma_tf32(float d[4], const uint32_t a[4],
                                         const uint32_t b0, const uint32_t b1) {
    asm volatile(
        "mma.sync.aligned.m16n8k8.row.col.f32.tf32.tf32.f32 "
        "{%0,%1,%2,%3}, {%4,%5,%6,%7}, {%8,%9}, {%0,%1,%2,%3};"
        : "+f"(d[0]), "+f"(d[1]), "+f"(d[2]), "+f"(d[3])
        : "r"(a[0]), "r"(a[1]), "r"(a[2]), "r"(a[3]), "r"(b0), "r"(b1));
}

__device__ __forceinline__ void cvt_tf32(uint32_t& r) {
    asm("cvt.rna.tf32.f32 %0, %0;" : "+r"(r));
}
__device__ __forceinline__ float round_tf32(float x) {
    uint32_t u = __float_as_uint(x);
    cvt_tf32(u);
    return __uint_as_float(u);
}

__device__ __forceinline__ void cp16(uint32_t dst, const void* src) {
    asm volatile("cp.async.cg.shared.global [%0], [%1], 16;"
                 :: "r"(dst), "l"(src) : "memory");
}
__device__ __forceinline__ void cp_commit() {
    asm volatile("cp.async.commit_group;" ::: "memory");
}
__device__ __forceinline__ void cp_wait0() {
    asm volatile("cp.async.wait_group 0;" ::: "memory");
}

// ------ weight prep: transpose + tf32 round: out[N,K] (fp32 storage) ------------
__global__ void wprep_kernel(const float* __restrict__ W,
                             float* __restrict__ ot, int K, int N)
{
    __shared__ float t[32][33];
    int k0 = blockIdx.y * 32, n0 = blockIdx.x * 32;
    int x = threadIdx.x, y = threadIdx.y;   // 32 x 8
#pragma unroll
    for (int r = 0; r < 32; r += 8)
        t[y + r][x] = W[(size_t)(k0 + y + r) * N + n0 + x];
    __syncthreads();
#pragma unroll
    for (int r = 0; r < 32; r += 8)
        ot[(size_t)(n0 + y + r) * K + k0 + x] = round_tf32(t[x][y + r]);
}

// ------------- TF32 HMMA GEMM: single pass, cp.async staging --------------------
// A [M,K] fp32 row-major; Bt [N,K] tf32 K-major. 512 thr / 16 warps,
// CTA tile 128x256, warp tile 32x64, BK=32 (128B rows, XOR-8 swizzle), dbl-buf.
// EPI: 2 = bias + LayerNorm over N==256, store C.
//      3 = bias + exact GELU + dot with w2, atomicAdd into logit[row]; no C.
// CVTA: round A fragments to tf32 in-kernel (0 if A pre-rounded in gmem).
template <int EPI, int CVTA>
__global__ __launch_bounds__(512, 1)
void gemm_mma(const float* __restrict__ A,
              const float* __restrict__ Bt,
              const float* __restrict__ bias,
              float* __restrict__ C,
              const float* __restrict__ w2,
              float* __restrict__ logit,
              int N, int K)
{
    extern __shared__ char smem[];
    constexpr int BM = 128, BN = 256;
    constexpr int R_B   = 16384;
    constexpr int STAGE = 49152;

    const int tid = threadIdx.x, wid = tid >> 5, lane = tid & 31;
    const int wm = wid & 3, wn = wid >> 2;
    const int row0 = blockIdx.y * BM, col0 = blockIdx.x * BN;
    const uint32_t sb = smem_u32(smem);

    float acc[2][8][4];
#pragma unroll
    for (int i = 0; i < 2; i++)
#pragma unroll
        for (int j = 0; j < 8; j++)
#pragma unroll
            for (int q = 0; q < 4; q++) acc[i][j][q] = 0.f;

    // ---------------- precomputed ldmatrix addresses ----------------
    const int ph = lane >> 4;
    uint32_t rdA[2], rdB[4];
#pragma unroll
    for (int mf = 0; mf < 2; mf++) {
        int r = wm * 32 + mf * 16 + (lane & 15);
        rdA[mf] = sb + (uint32_t)(r * 128 + ((ph ^ (r & 7)) << 4));
    }
#pragma unroll
    for (int nf2 = 0; nf2 < 4; nf2++) {
        int r = wn * 64 + nf2 * 16 + (lane & 15);
        rdB[nf2] = sb + R_B + (uint32_t)(r * 128 + ((ph ^ (r & 7)) << 4));
    }

    // cp.async destinations
    const int ar  = tid >> 2;
    const int ac0 = (tid & 3) * 2;
    uint32_t wrA = sb + (uint32_t)(ar * 128 + ((ac0 ^ (ar & 7)) << 4));
    const int br  = tid >> 1;
    const int bc0 = (tid & 1) * 4;
    uint32_t wrB = sb + R_B + (uint32_t)(br * 128 + ((bc0 ^ (br & 7)) << 4));

    const char* pA = (const char*)(A + (size_t)(row0 + ar) * K + ac0 * 4);
    const char* pB = (const char*)(Bt + (size_t)(col0 + br) * K + bc0 * 4);

    auto issue = [&](int k0) {
        size_t off = (size_t)k0 * 4;
        cp16(wrA,       pA + off);
        cp16(wrA ^ 16u, pA + off + 16);
#pragma unroll
        for (int j = 0; j < 4; j++)
            cp16(wrB ^ (uint32_t)(j << 4), pB + off + j * 16);
    };

    // ---------------- prologue ----------------
    issue(0);
    cp_commit();
    cp_wait0();
    __syncthreads();
    wrA += STAGE; wrB += STAGE;

    // ---------------- mainloop: BK=32, 4 k8-steps per chunk ----------------
    const int nc = K >> 5;
    for (int c = 0; c < nc; c++) {
        const bool more = (c + 1 < nc);
        if (more) { issue((c + 1) << 5); cp_commit(); }

#pragma unroll
        for (int ks = 0; ks < 4; ks++) {
            const uint32_t kx = (uint32_t)(ks << 5);
            uint32_t a[2][4];
            ldm4(a[0], rdA[0] ^ kx);
            ldm4(a[1], rdA[1] ^ kx);
            if (CVTA) {
#pragma unroll
                for (int mf = 0; mf < 2; mf++)
#pragma unroll
                    for (int q = 0; q < 4; q++) cvt_tf32(a[mf][q]);
            }
#pragma unroll
            for (int nf2 = 0; nf2 < 4; nf2++) {
                uint32_t t[4];
                ldm4(t, rdB[nf2] ^ kx);
#pragma unroll
                for (int mf = 0; mf < 2; mf++) {
                    mma_tf32(acc[mf][2 * nf2],     a[mf], t[0], t[2]);
                    mma_tf32(acc[mf][2 * nf2 + 1], a[mf], t[1], t[3]);
                }
            }
        }

        if (more) {
            cp_wait0();
            __syncthreads();
            const int d = (c & 1) ? -STAGE : STAGE;
            rdA[0] += d; rdA[1] += d;
#pragma unroll
            for (int i = 0; i < 4; i++) rdB[i] += d;
            wrA -= d; wrB -= d;
        }
    }

    // ------------------------------- epilogue -----------------------------------
    __syncthreads();
    const int r4 = lane >> 2, c2 = (lane & 3) * 2;
    float2 bs[8];
#pragma unroll
    for (int nf = 0; nf < 8; nf++)
        bs[nf] = *(const float2*)&bias[col0 + wn * 64 + nf * 8 + c2];

    if (EPI == 3) {
        // GELU + partial dot with w2 -> logit[row]
        float2 ws[8];
#pragma unroll
        for (int nf = 0; nf < 8; nf++)
            ws[nf] = *(const float2*)&w2[col0 + wn * 64 + nf * 8 + c2];
#pragma unroll
        for (int mf = 0; mf < 2; mf++)
#pragma unroll
            for (int h = 0; h < 2; h++) {
                float s = 0.f;
#pragma unroll
                for (int nf = 0; nf < 8; nf++) {
                    float v0 = acc[mf][nf][2 * h]     + bs[nf].x;
                    float v1 = acc[mf][nf][2 * h + 1] + bs[nf].y;
                    v0 = 0.5f * v0 * (1.0f + erff(v0 * 0.70710678118654752f));
                    v1 = 0.5f * v1 * (1.0f + erff(v1 * 0.70710678118654752f));
                    s += v0 * ws[nf].x + v1 * ws[nf].y;
                }
                s += __shfl_xor_sync(0xffffffffu, s, 1);
                s += __shfl_xor_sync(0xffffffffu, s, 2);
                if ((lane & 3) == 0) {
                    int row = row0 + wm * 32 + mf * 16 + h * 8 + r4;
                    atomicAdd(&logit[row], s);
                }
            }
        return;
    }

    // EPI == 2: LayerNorm over 256 cols, store C
    float mu[2][2], inv[2][2];
    {
        float2* part = (float2*)(smem + 2 * STAGE);  // [BM][4]
#pragma unroll
        for (int mf = 0; mf < 2; mf++)
#pragma unroll
            for (int h = 0; h < 2; h++) {
                float s1 = 0.f, s2 = 0.f;
#pragma unroll
                for (int nf = 0; nf < 8; nf++) {
                    float v0 = acc[mf][nf][2 * h]     + bs[nf].x;
                    float v1 = acc[mf][nf][2 * h + 1] + bs[nf].y;
                    s1 += v0 + v1; s2 += v0 * v0 + v1 * v1;
                }
                s1 += __shfl_xor_sync(0xffffffffu, s1, 1);
                s2 += __shfl_xor_sync(0xffffffffu, s2, 1);
                s1 += __shfl_xor_sync(0xffffffffu, s1, 2);
                s2 += __shfl_xor_sync(0xffffffffu, s2, 2);
                int rt = wm * 32 + mf * 16 + h * 8 + r4;
                if ((lane & 3) == 0) part[rt * 4 + wn] = make_float2(s1, s2);
            }
        __syncthreads();
#pragma unroll
        for (int mf = 0; mf < 2; mf++)
#pragma unroll
            for (int h = 0; h < 2; h++) {
                int rt = wm * 32 + mf * 16 + h * 8 + r4;
                float s1 = 0.f, s2 = 0.f;
#pragma unroll
                for (int w = 0; w < 4; w++) {
                    float2 p = part[rt * 4 + w];
                    s1 += p.x; s2 += p.y;
                }
                float m = s1 * (1.0f / 256.0f);
                float var = s2 * (1.0f / 256.0f) - m * m;
                mu[mf][h] = m;
                inv[mf][h] = rsqrtf(var + 1e-5f);
            }
    }

#pragma unroll
    for (int mf = 0; mf < 2; mf++)
#pragma unroll
        for (int h = 0; h < 2; h++) {
            int row = row0 + wm * 32 + mf * 16 + h * 8 + r4;
#pragma unroll
            for (int nf = 0; nf < 8; nf++) {
                float v0 = (acc[mf][nf][2 * h]     + bs[nf].x - mu[mf][h]) * inv[mf][h];
                float v1 = (acc[mf][nf][2 * h + 1] + bs[nf].y - mu[mf][h]) * inv[mf][h];
                int col = col0 + wn * 64 + nf * 8 + c2;
                *(float2*)&C[(size_t)row * N + col] = make_float2(v0, v1);
            }
        }
}

// -------- fused fractional shift + causal window context: g_actx from g_a -------
__global__ void ctx_kernel(const float* __restrict__ theta)
{
    const int t = blockIdx.x;
    const int b = blockIdx.y;
    const int d = threadIdx.x;

    float th    = fminf(fmaxf(theta[0], -12.f), 12.f);
    float delta = 2.0f + 4.0f / (1.0f + expf(-th));
    float dl    = fminf(fmaxf(delta, 0.f), (float)(T_ - 1));
    float nf    = floorf(dl);
    float alpha = dl - nf;
    int   ni    = (int)nf;

    float center = fminf(fmaxf((float)t + delta, 0.f), (float)t);
    int lo = max(0, (int)floorf(center - 5.0f) - 1);
    int hi = min(t, (int)ceilf (center + 5.0f) + 1);

    const float* ab = g_a + (size_t)b * T_ * DM_;
    float sum = 0.f; int cnt = 0;
    for (int tau = lo; tau <= hi; tau++) {
        if (fabsf((float)tau - center) <= 5.0f) {
            cnt++;
            int i0 = min(max(tau - ni, 0), T_ - 1);
            int i1 = min(i0 + 1, T_ - 1);
            sum += (1.0f - alpha) * ab[i0 * DM_ + d] + alpha * ab[i1 * DM_ + d];
        }
    }
    g_actx[((size_t)b * T_ + t) * DM_ + d] = sum / fmaxf((float)cnt, 1e-8f);
}

// -- build X = [an, vn, an*vn] tf32-rounded, with L2 normalization (warp/row) ----
__global__ void buildx_kernel()
{
    const int row  = blockIdx.x * 8 + (threadIdx.x >> 5);
    const int lane = threadIdx.x & 31;
    const float* v  = g_v    + (size_t)row * DM_;
    const float* ac = g_actx + (size_t)row * DM_;

    float vv[8], aa[8];
    float sv = 0.f, sa = 0.f;
#pragma unroll
    for (int i = 0; i < 8; i++) {
        vv[i] = v[lane + 32 * i];
        aa[i] = ac[lane + 32 * i];
        sv += vv[i] * vv[i];
        sa += aa[i] * aa[i];
    }
#pragma unroll
    for (int o = 16; o > 0; o >>= 1) {
        sv += __shfl_xor_sync(0xffffffffu, sv, o);
        sa += __shfl_xor_sync(0xffffffffu, sa, o);
    }
    float iv = 1.0f / fmaxf(sqrtf(sv), 1e-8f);
    float ia = 1.0f / fmaxf(sqrtf(sa), 1e-8f);

    float* x = g_x + (size_t)row * (3 * DM_);
#pragma unroll
    for (int i = 0; i < 8; i++) {
        int d = lane + 32 * i;
        float an = aa[i] * ia, vn = vv[i] * iv;
        x[d]           = round_tf32(an);
        x[DM_ + d]     = round_tf32(vn);
        x[2 * DM_ + d] = round_tf32(an * vn);
    }
}

// -------- gate: logit -> sigmoid -> blend: out = g*a_ctx + (1-g)*v --------------
__global__ void gate_kernel(const float* __restrict__ b2, float* __restrict__ out)
{
    const int row = blockIdx.x;
    const int tid = threadIdx.x;
    float logitv = fminf(fmaxf(g_logit[row] + b2[0], -12.f), 12.f);
    float g = 1.0f / (1.0f + expf(-logitv));
    g = fminf(fmaxf(g, 0.05f), 0.95f);
    float ac = g_actx[(size_t)row * DM_ + tid];
    float v  = g_v  [(size_t)row * DM_ + tid];
    out[(size_t)row * DM_ + tid] = g * ac + (1.0f - g) * v;
}

// --------------------------------- launcher ------------------------------------
extern "C" void kernel_launch(void* const* d_in, const int* in_sizes, int n_in,
                              void* d_out, int out_size)
{
    const float* video = (const float*)d_in[0];
    const float* audio = (const float*)d_in[1];
    const float* Wv    = (const float*)d_in[2];
    const float* bv    = (const float*)d_in[3];
    const float* Wa    = (const float*)d_in[4];
    const float* ba    = (const float*)d_in[5];
    const float* theta = (const float*)d_in[6];
    const float* W1    = (const float*)d_in[7];
    const float* b1    = (const float*)d_in[8];
    const float* W2    = (const float*)d_in[9];
    const float* b2    = (const float*)d_in[10];
    float* out = (float*)d_out;

    float *pv, *pa, *px, *plog, *wvt, *wat, *w1t;
    cudaGetSymbolAddress((void**)&pv,   g_v);
    cudaGetSymbolAddress((void**)&pa,   g_a);
    cudaGetSymbolAddress((void**)&px,   g_x);
    cudaGetSymbolAddress((void**)&plog, g_logit);
    cudaGetSymbolAddress((void**)&wvt,  g_wvt);
    cudaGetSymbolAddress((void**)&wat,  g_wat);
    cudaGetSymbolAddress((void**)&w1t,  g_w1t);

    const int SMEM = 2 * 49152 + 128 * 4 * 8;   // 102400
    cudaFuncSetAttribute((const void*)gemm_mma<2, 1>,
                         cudaFuncAttributeMaxDynamicSharedMemorySize, SMEM);
    cudaFuncSetAttribute((const void*)gemm_mma<3, 0>,
                         cudaFuncAttributeMaxDynamicSharedMemorySize, SMEM);

    cudaMemsetAsync(plog, 0, ROWS * sizeof(float));

    dim3 wblk(32, 8);
    wprep_kernel<<<dim3(DM_  / 32, 1024 / 32), wblk>>>(Wv, wvt, 1024, DM_);
    wprep_kernel<<<dim3(DM_  / 32,  768 / 32), wblk>>>(Wa, wat,  768, DM_);
    wprep_kernel<<<dim3(HID_ / 32,  768 / 32), wblk>>>(W1, w1t,  768, HID_);

    dim3 blk(512);
    // v = LN(video @ Wv + bv)   M=16384 K=1024 N=256
    gemm_mma<2, 1><<<dim3(1, ROWS / 128), blk, SMEM>>>(video, wvt, bv, pv,
                                                       nullptr, nullptr, DM_, 1024);
    // a = LN(audio @ Wa + ba)   M=16384 K=768  N=256
    gemm_mma<2, 1><<<dim3(1, ROWS / 128), blk, SMEM>>>(audio, wat, ba, pa,
                                                       nullptr, nullptr, DM_, 768);
    // a_ctx
    ctx_kernel<<<dim3(T_, B_), dim3(256)>>>(theta);
    // X = [an, vn, an*vn] (tf32-rounded)
    buildx_kernel<<<ROWS / 8, dim3(256)>>>();
    // logits += gelu(X @ W1 + b1) . W2   (no h materialization)
    gemm_mma<3, 0><<<dim3(HID_ / 256, ROWS / 128), blk, SMEM>>>(px, w1t, b1, nullptr,
                                                                W2, plog, HID_, 768);
    // gate + blend
    gate_kernel<<<ROWS, dim3(256)>>>(b2, out);
}

// round 10
// speedup vs baseline: 1.6306x; 1.0457x over previous
#include <cuda_runtime.h>
#include <cuda_bf16.h>
#include <math.h>
#include <stdint.h>

#define B_   8
#define T_   2048
#define DM_  256
#define HID_ 1024
#define ROWS (B_ * T_)   // 16384

// ---------------- scratch (static device globals; no allocation) ----------------
__device__ float g_v   [ROWS * DM_];
__device__ float g_a   [ROWS * DM_];
__device__ float g_actx[ROWS * DM_];
__device__ float g_x   [ROWS * 3 * DM_];   // tf32-rounded
__device__ float g_logit[ROWS];

// transposed weights, tf32-rounded fp32: [N, K] K-major
__device__ float g_wvt[DM_ * 1024];
__device__ float g_wat[DM_ * 768];
__device__ float g_w1t[HID_ * 768];

// ------------------------------- helpers ----------------------------------------
__device__ __forceinline__ uint32_t smem_u32(const void* p) {
    uint32_t a;
    asm("{ .reg .u64 t; cvta.to.shared.u64 t, %1; cvt.u32.u64 %0, t; }"
        : "=r"(a) : "l"(p));
    return a;
}

__device__ __forceinline__ void ldm4(uint32_t r[4], uint32_t addr) {
    asm volatile("ldmatrix.sync.aligned.m8n8.x4.shared.b16 {%0,%1,%2,%3}, [%4];"
        : "=r"(r[0]), "=r"(r[1]), "=r"(r[2]), "=r"(r[3]) : "r"(addr));
}

__device__ __forceinline__ void mma_tf32(float d[4], const uint32_t a[4],
                                         const uint32_t b0, const uint32_t b1) {
    asm volatile(
        "mma.sync.aligned.m16n8k8.row.col.f32.tf32.tf32.f32 "
        "{%0,%1,%2,%3}, {%4,%5,%6,%7}, {%8,%9}, {%0,%1,%2,%3};"
        : "+f"(d[0]), "+f"(d[1]), "+f"(d[2]), "+f"(d[3])
        : "r"(a[0]), "r"(a[1]), "r"(a[2]), "r"(a[3]), "r"(b0), "r"(b1));
}

__device__ __forceinline__ void cvt_tf32(uint32_t& r) {
    asm("cvt.rna.tf32.f32 %0, %0;" : "+r"(r));
}
__device__ __forceinline__ float round_tf32(float x) {
    uint32_t u = __float_as_uint(x);
    cvt_tf32(u);
    return __uint_as_float(u);
}

__device__ __forceinline__ void cp16(uint32_t dst, const void* src) {
    asm volatile("cp.async.cg.shared.global [%0], [%1], 16;"
                 :: "r"(dst), "l"(src) : "memory");
}
__device__ __forceinline__ void cp_commit() {
    asm volatile("cp.async.commit_group;" ::: "memory");
}
__device__ __forceinline__ void cp_wait2() {
    asm volatile("cp.async.wait_group 2;" ::: "memory");
}

// ------ weight prep: transpose + tf32 round: out[N,K] (fp32 storage) ------------
__global__ void wprep_kernel(const float* __restrict__ W,
                             float* __restrict__ ot, int K, int N)
{
    __shared__ float t[32][33];
    int k0 = blockIdx.y * 32, n0 = blockIdx.x * 32;
    int x = threadIdx.x, y = threadIdx.y;   // 32 x 8
#pragma unroll
    for (int r = 0; r < 32; r += 8)
        t[y + r][x] = W[(size_t)(k0 + y + r) * N + n0 + x];
    __syncthreads();
#pragma unroll
    for (int r = 0; r < 32; r += 8)
        ot[(size_t)(n0 + y + r) * K + k0 + x] = round_tf32(t[x][y + r]);
}

// ------------- TF32 HMMA GEMM: 4-stage cp.async pipeline ------------------------
// A [M,K] fp32 row-major; Bt [N,K] tf32 K-major. 512 thr / 16 warps,
// CTA tile 128x256, warp tile 32x64, BK=32 (128B rows, XOR-8 swizzle), 4 stages.
// EPI: 2 = bias + LayerNorm over N==256, store C.
//      3 = bias + exact GELU + dot with w2, atomicAdd into logit[row]; no C.
// CVTA: round A fragments to tf32 in-kernel (0 if A pre-rounded in gmem).
template <int EPI, int CVTA>
__global__ __launch_bounds__(512, 1)
void gemm_mma(const float* __restrict__ A,
              const float* __restrict__ Bt,
              const float* __restrict__ bias,
              float* __restrict__ C,
              const float* __restrict__ w2,
              float* __restrict__ logit,
              int N, int K)
{
    extern __shared__ char smem[];
    constexpr int BM = 128, BN = 256;
    constexpr int R_B   = 16384;
    constexpr int STAGE = 49152;

    const int tid = threadIdx.x, wid = tid >> 5, lane = tid & 31;
    const int wm = wid & 3, wn = wid >> 2;
    const int row0 = blockIdx.y * BM, col0 = blockIdx.x * BN;
    const uint32_t sb = smem_u32(smem);

    float acc[2][8][4];
#pragma unroll
    for (int i = 0; i < 2; i++)
#pragma unroll
        for (int j = 0; j < 8; j++)
#pragma unroll
            for (int q = 0; q < 4; q++) acc[i][j][q] = 0.f;

    // ---------------- precomputed ldmatrix addresses (stage 0) ----------------
    const int ph = lane >> 4;
    uint32_t rdA[2], rdB[4];
#pragma unroll
    for (int mf = 0; mf < 2; mf++) {
        int r = wm * 32 + mf * 16 + (lane & 15);
        rdA[mf] = sb + (uint32_t)(r * 128 + ((ph ^ (r & 7)) << 4));
    }
#pragma unroll
    for (int nf2 = 0; nf2 < 4; nf2++) {
        int r = wn * 64 + nf2 * 16 + (lane & 15);
        rdB[nf2] = sb + R_B + (uint32_t)(r * 128 + ((ph ^ (r & 7)) << 4));
    }

    // cp.async destinations (stage 0)
    const int ar  = tid >> 2;
    const int ac0 = (tid & 3) * 2;
    uint32_t wrA = sb + (uint32_t)(ar * 128 + ((ac0 ^ (ar & 7)) << 4));
    const int br  = tid >> 1;
    const int bc0 = (tid & 1) * 4;
    uint32_t wrB = sb + R_B + (uint32_t)(br * 128 + ((bc0 ^ (br & 7)) << 4));

    const char* pA = (const char*)(A + (size_t)(row0 + ar) * K + ac0 * 4);
    const char* pB = (const char*)(Bt + (size_t)(col0 + br) * K + bc0 * 4);

    auto issue = [&](int k0) {
        size_t off = (size_t)k0 * 4;
        cp16(wrA,       pA + off);
        cp16(wrA ^ 16u, pA + off + 16);
#pragma unroll
        for (int j = 0; j < 4; j++)
            cp16(wrB ^ (uint32_t)(j << 4), pB + off + j * 16);
    };

    // ---------------- prologue: stages 0..2 ----------------
    const int nc = K >> 5;
#pragma unroll
    for (int s = 0; s < 3; s++) {
        issue(s << 5);
        cp_commit();
        wrA += STAGE; wrB += STAGE;           // now at stage s+1
    }
    // wr now at stage 3

    // ---------------- mainloop ----------------
    for (int c = 0; c < nc; c++) {
        cp_wait2();           // chunk c complete (<=2 newer groups pending)
        __syncthreads();      // all threads' group c visible; stage (c+3)&3 free

        if (c + 3 < nc) issue((c + 3) << 5);
        cp_commit();          // unconditional: keeps group numbering aligned
        {   // advance write stage: (c+3)&3 -> (c+4)&3
            const int wd = (((c + 3) & 3) == 3) ? -3 * STAGE : STAGE;
            wrA += wd; wrB += wd;
        }

#pragma unroll
        for (int ks = 0; ks < 4; ks++) {
            const uint32_t kx = (uint32_t)(ks << 5);
            uint32_t a[2][4];
            ldm4(a[0], rdA[0] ^ kx);
            ldm4(a[1], rdA[1] ^ kx);
            if (CVTA) {
#pragma unroll
                for (int mf = 0; mf < 2; mf++)
#pragma unroll
                    for (int q = 0; q < 4; q++) cvt_tf32(a[mf][q]);
            }
#pragma unroll
            for (int nf2 = 0; nf2 < 4; nf2++) {
                uint32_t t[4];
                ldm4(t, rdB[nf2] ^ kx);
#pragma unroll
                for (int mf = 0; mf < 2; mf++) {
                    mma_tf32(acc[mf][2 * nf2],     a[mf], t[0], t[2]);
                    mma_tf32(acc[mf][2 * nf2 + 1], a[mf], t[1], t[3]);
                }
            }
        }

        {   // advance read stage: c&3 -> (c+1)&3
            const int rd = ((c & 3) == 3) ? -3 * STAGE : STAGE;
            rdA[0] += rd; rdA[1] += rd;
#pragma unroll
            for (int i = 0; i < 4; i++) rdB[i] += rd;
        }
    }

    // ------------------------------- epilogue -----------------------------------
    __syncthreads();
    const int r4 = lane >> 2, c2 = (lane & 3) * 2;
    float2 bs[8];
#pragma unroll
    for (int nf = 0; nf < 8; nf++)
        bs[nf] = *(const float2*)&bias[col0 + wn * 64 + nf * 8 + c2];

    if (EPI == 3) {
        // GELU + partial dot with w2 -> logit[row]
        float2 ws[8];
#pragma unroll
        for (int nf = 0; nf < 8; nf++)
            ws[nf] = *(const float2*)&w2[col0 + wn * 64 + nf * 8 + c2];
#pragma unroll
        for (int mf = 0; mf < 2; mf++)
#pragma unroll
            for (int h = 0; h < 2; h++) {
                float s = 0.f;
#pragma unroll
                for (int nf = 0; nf < 8; nf++) {
                    float v0 = acc[mf][nf][2 * h]     + bs[nf].x;
                    float v1 = acc[mf][nf][2 * h + 1] + bs[nf].y;
                    v0 = 0.5f * v0 * (1.0f + erff(v0 * 0.70710678118654752f));
                    v1 = 0.5f * v1 * (1.0f + erff(v1 * 0.70710678118654752f));
                    s += v0 * ws[nf].x + v1 * ws[nf].y;
                }
                s += __shfl_xor_sync(0xffffffffu, s, 1);
                s += __shfl_xor_sync(0xffffffffu, s, 2);
                if ((lane & 3) == 0) {
                    int row = row0 + wm * 32 + mf * 16 + h * 8 + r4;
                    atomicAdd(&logit[row], s);
                }
            }
        return;
    }

    // EPI == 2: LayerNorm over 256 cols, store C
    float mu[2][2], inv[2][2];
    {
        float2* part = (float2*)(smem + 4 * STAGE);  // [BM][4]
#pragma unroll
        for (int mf = 0; mf < 2; mf++)
#pragma unroll
            for (int h = 0; h < 2; h++) {
                float s1 = 0.f, s2 = 0.f;
#pragma unroll
                for (int nf = 0; nf < 8; nf++) {
                    float v0 = acc[mf][nf][2 * h]     + bs[nf].x;
                    float v1 = acc[mf][nf][2 * h + 1] + bs[nf].y;
                    s1 += v0 + v1; s2 += v0 * v0 + v1 * v1;
                }
                s1 += __shfl_xor_sync(0xffffffffu, s1, 1);
                s2 += __shfl_xor_sync(0xffffffffu, s2, 1);
                s1 += __shfl_xor_sync(0xffffffffu, s1, 2);
                s2 += __shfl_xor_sync(0xffffffffu, s2, 2);
                int rt = wm * 32 + mf * 16 + h * 8 + r4;
                if ((lane & 3) == 0) part[rt * 4 + wn] = make_float2(s1, s2);
            }
        __syncthreads();
#pragma unroll
        for (int mf = 0; mf < 2; mf++)
#pragma unroll
            for (int h = 0; h < 2; h++) {
                int rt = wm * 32 + mf * 16 + h * 8 + r4;
                float s1 = 0.f, s2 = 0.f;
#pragma unroll
                for (int w = 0; w < 4; w++) {
                    float2 p = part[rt * 4 + w];
                    s1 += p.x; s2 += p.y;
                }
                float m = s1 * (1.0f / 256.0f);
                float var = s2 * (1.0f / 256.0f) - m * m;
                mu[mf][h] = m;
                inv[mf][h] = rsqrtf(var + 1e-5f);
            }
    }

#pragma unroll
    for (int mf = 0; mf < 2; mf++)
#pragma unroll
        for (int h = 0; h < 2; h++) {
            int row = row0 + wm * 32 + mf * 16 + h * 8 + r4;
#pragma unroll
            for (int nf = 0; nf < 8; nf++) {
                float v0 = (acc[mf][nf][2 * h]     + bs[nf].x - mu[mf][h]) * inv[mf][h];
                float v1 = (acc[mf][nf][2 * h + 1] + bs[nf].y - mu[mf][h]) * inv[mf][h];
                int col = col0 + wn * 64 + nf * 8 + c2;
                *(float2*)&C[(size_t)row * N + col] = make_float2(v0, v1);
            }
        }
}

// -------- fused fractional shift + causal window context: g_actx from g_a -------
__global__ void ctx_kernel(const float* __restrict__ theta)
{
    const int t = blockIdx.x;
    const int b = blockIdx.y;
    const int d = threadIdx.x;

    float th    = fminf(fmaxf(theta[0], -12.f), 12.f);
    float delta = 2.0f + 4.0f / (1.0f + expf(-th));
    float dl    = fminf(fmaxf(delta, 0.f), (float)(T_ - 1));
    float nf    = floorf(dl);
    float alpha = dl - nf;
    int   ni    = (int)nf;

    float center = fminf(fmaxf((float)t + delta, 0.f), (float)t);
    int lo = max(0, (int)floorf(center - 5.0f) - 1);
    int hi = min(t, (int)ceilf (center + 5.0f) + 1);

    const float* ab = g_a + (size_t)b * T_ * DM_;
    float sum = 0.f; int cnt = 0;
    for (int tau = lo; tau <= hi; tau++) {
        if (fabsf((float)tau - center) <= 5.0f) {
            cnt++;
            int i0 = min(max(tau - ni, 0), T_ - 1);
            int i1 = min(i0 + 1, T_ - 1);
            sum += (1.0f - alpha) * ab[i0 * DM_ + d] + alpha * ab[i1 * DM_ + d];
        }
    }
    g_actx[((size_t)b * T_ + t) * DM_ + d] = sum / fmaxf((float)cnt, 1e-8f);
}

// -- build X = [an, vn, an*vn] tf32-rounded, with L2 normalization (warp/row) ----
__global__ void buildx_kernel()
{
    const int row  = blockIdx.x * 8 + (threadIdx.x >> 5);
    const int lane = threadIdx.x & 31;
    const float* v  = g_v    + (size_t)row * DM_;
    const float* ac = g_actx + (size_t)row * DM_;

    float vv[8], aa[8];
    float sv = 0.f, sa = 0.f;
#pragma unroll
    for (int i = 0; i < 8; i++) {
        vv[i] = v[lane + 32 * i];
        aa[i] = ac[lane + 32 * i];
        sv += vv[i] * vv[i];
        sa += aa[i] * aa[i];
    }
#pragma unroll
    for (int o = 16; o > 0; o >>= 1) {
        sv += __shfl_xor_sync(0xffffffffu, sv, o);
        sa += __shfl_xor_sync(0xffffffffu, sa, o);
    }
    float iv = 1.0f / fmaxf(sqrtf(sv), 1e-8f);
    float ia = 1.0f / fmaxf(sqrtf(sa), 1e-8f);

    float* x = g_x + (size_t)row * (3 * DM_);
#pragma unroll
    for (int i = 0; i < 8; i++) {
        int d = lane + 32 * i;
        float an = aa[i] * ia, vn = vv[i] * iv;
        x[d]           = round_tf32(an);
        x[DM_ + d]     = round_tf32(vn);
        x[2 * DM_ + d] = round_tf32(an * vn);
    }
}

// -------- gate: logit -> sigmoid -> blend: out = g*a_ctx + (1-g)*v --------------
__global__ void gate_kernel(const float* __restrict__ b2, float* __restrict__ out)
{
    const int row = blockIdx.x;
    const int tid = threadIdx.x;
    float logitv = fminf(fmaxf(g_logit[row] + b2[0], -12.f), 12.f);
    float g = 1.0f / (1.0f + expf(-logitv));
    g = fminf(fmaxf(g, 0.05f), 0.95f);
    float ac = g_actx[(size_t)row * DM_ + tid];
    float v  = g_v  [(size_t)row * DM_ + tid];
    out[(size_t)row * DM_ + tid] = g * ac + (1.0f - g) * v;
}

// --------------------------------- launcher ------------------------------------
extern "C" void kernel_launch(void* const* d_in, const int* in_sizes, int n_in,
                              void* d_out, int out_size)
{
    const float* video = (const float*)d_in[0];
    const float* audio = (const float*)d_in[1];
    const float* Wv    = (const float*)d_in[2];
    const float* bv    = (const float*)d_in[3];
    const float* Wa    = (const float*)d_in[4];
    const float* ba    = (const float*)d_in[5];
    const float* theta = (const float*)d_in[6];
    const float* W1    = (const float*)d_in[7];
    const float* b1    = (const float*)d_in[8];
    const float* W2    = (const float*)d_in[9];
    const float* b2    = (const float*)d_in[10];
    float* out = (float*)d_out;

    float *pv, *pa, *px, *plog, *wvt, *wat, *w1t;
    cudaGetSymbolAddress((void**)&pv,   g_v);
    cudaGetSymbolAddress((void**)&pa,   g_a);
    cudaGetSymbolAddress((void**)&px,   g_x);
    cudaGetSymbolAddress((void**)&plog, g_logit);
    cudaGetSymbolAddress((void**)&wvt,  g_wvt);
    cudaGetSymbolAddress((void**)&wat,  g_wat);
    cudaGetSymbolAddress((void**)&w1t,  g_w1t);

    const int SMEM = 4 * 49152 + 128 * 4 * 8;   // 200704
    cudaFuncSetAttribute((const void*)gemm_mma<2, 1>,
                         cudaFuncAttributeMaxDynamicSharedMemorySize, SMEM);
    cudaFuncSetAttribute((const void*)gemm_mma<3, 0>,
                         cudaFuncAttributeMaxDynamicSharedMemorySize, SMEM);

    cudaMemsetAsync(plog, 0, ROWS * sizeof(float));

    dim3 wblk(32, 8);
    wprep_kernel<<<dim3(DM_  / 32, 1024 / 32), wblk>>>(Wv, wvt, 1024, DM_);
    wprep_kernel<<<dim3(DM_  / 32,  768 / 32), wblk>>>(Wa, wat,  768, DM_);
    wprep_kernel<<<dim3(HID_ / 32,  768 / 32), wblk>>>(W1, w1t,  768, HID_);

    dim3 blk(512);
    // v = LN(video @ Wv + bv)   M=16384 K=1024 N=256
    gemm_mma<2, 1><<<dim3(1, ROWS / 128), blk, SMEM>>>(video, wvt, bv, pv,
                                                       nullptr, nullptr, DM_, 1024);
    // a = LN(audio @ Wa + ba)   M=16384 K=768  N=256
    gemm_mma<2, 1><<<dim3(1, ROWS / 128), blk, SMEM>>>(audio, wat, ba, pa,
                                                       nullptr, nullptr, DM_, 768);
    // a_ctx
    ctx_kernel<<<dim3(T_, B_), dim3(256)>>>(theta);
    // X = [an, vn, an*vn] (tf32-rounded)
    buildx_kernel<<<ROWS / 8, dim3(256)>>>();
    // logits += gelu(X @ W1 + b1) . W2   (no h materialization)
    gemm_mma<3, 0><<<dim3(HID_ / 256, ROWS / 128), blk, SMEM>>>(px, w1t, b1, nullptr,
                                                                W2, plog, HID_, 768);
    // gate + blend
    gate_kernel<<<ROWS, dim3(256)>>>(b2, out);
}

// round 11
// speedup vs baseline: 1.6652x; 1.0212x over previous
#include <cuda_runtime.h>
#include <cuda_bf16.h>
#include <math.h>
#include <stdint.h>

#define B_   8
#define T_   2048
#define DM_  256
#define HID_ 1024
#define ROWS (B_ * T_)   // 16384

// ---------------- scratch (static device globals; no allocation) ----------------
__device__ float g_v   [ROWS * DM_];
__device__ float g_a   [ROWS * DM_];
__device__ float g_actx[ROWS * DM_];
__device__ float g_x   [ROWS * 3 * DM_];   // tf32-rounded
__device__ float g_logit[ROWS];

// transposed weights, tf32-rounded fp32: [N, K] K-major
__device__ float g_wvt[DM_ * 1024];
__device__ float g_wat[DM_ * 768];
__device__ float g_w1t[HID_ * 768];

// ------------------------------- helpers ----------------------------------------
__device__ __forceinline__ uint32_t smem_u32(const void* p) {
    uint32_t a;
    asm("{ .reg .u64 t; cvta.to.shared.u64 t, %1; cvt.u32.u64 %0, t; }"
        : "=r"(a) : "l"(p));
    return a;
}

__device__ __forceinline__ void ldm4(uint32_t r[4], uint32_t addr) {
    asm volatile("ldmatrix.sync.aligned.m8n8.x4.shared.b16 {%0,%1,%2,%3}, [%4];"
        : "=r"(r[0]), "=r"(r[1]), "=r"(r[2]), "=r"(r[3]) : "r"(addr));
}

__device__ __forceinline__ void mma_tf32(float d[4], const uint32_t a[4],
                                         const uint32_t b0, const uint32_t b1) {
    asm volatile(
        "mma.sync.aligned.m16n8k8.row.col.f32.tf32.tf32.f32 "
        "{%0,%1,%2,%3}, {%4,%5,%6,%7}, {%8,%9}, {%0,%1,%2,%3};"
        : "+f"(d[0]), "+f"(d[1]), "+f"(d[2]), "+f"(d[3])
        : "r"(a[0]), "r"(a[1]), "r"(a[2]), "r"(a[3]), "r"(b0), "r"(b1));
}

__device__ __forceinline__ void cvt_tf32(uint32_t& r) {
    asm("cvt.rna.tf32.f32 %0, %0;" : "+r"(r));
}
__device__ __forceinline__ float round_tf32(float x) {
    uint32_t u = __float_as_uint(x);
    cvt_tf32(u);
    return __uint_as_float(u);
}

__device__ __forceinline__ void cp16(uint32_t dst, const void* src) {
    asm volatile("cp.async.cg.shared.global [%0], [%1], 16;"
                 :: "r"(dst), "l"(src) : "memory");
}
__device__ __forceinline__ void cp_commit() {
    asm volatile("cp.async.commit_group;" ::: "memory");
}
__device__ __forceinline__ void cp_wait2() {
    asm volatile("cp.async.wait_group 2;" ::: "memory");
}
__device__ __forceinline__ void cp_wait1() {
    asm volatile("cp.async.wait_group 1;" ::: "memory");
}

// ------ weight prep: transpose + tf32 round: out[N,K] (fp32 storage) ------------
__global__ void wprep_kernel(const float* __restrict__ W,
                             float* __restrict__ ot, int K, int N)
{
    __shared__ float t[32][33];
    int k0 = blockIdx.y * 32, n0 = blockIdx.x * 32;
    int x = threadIdx.x, y = threadIdx.y;   // 32 x 8
#pragma unroll
    for (int r = 0; r < 32; r += 8)
        t[y + r][x] = W[(size_t)(k0 + y + r) * N + n0 + x];
    __syncthreads();
#pragma unroll
    for (int r = 0; r < 32; r += 8)
        ot[(size_t)(n0 + y + r) * K + k0 + x] = round_tf32(t[x][y + r]);
}

// ------------- TF32 HMMA GEMM (LN): 4-stage cp.async pipeline -------------------
// 512 thr / 16 warps, CTA tile 128x256, warp tile 32x64, BK=32, 4 stages.
// EPI 2 = bias + LayerNorm over N==256, store C.  CVTA = round A in-kernel.
template <int EPI, int CVTA>
__global__ __launch_bounds__(512, 1)
void gemm_mma(const float* __restrict__ A,
              const float* __restrict__ Bt,
              const float* __restrict__ bias,
              float* __restrict__ C,
              int N, int K)
{
    extern __shared__ char smem[];
    constexpr int R_B   = 16384;
    constexpr int STAGE = 49152;

    const int tid = threadIdx.x, wid = tid >> 5, lane = tid & 31;
    const int wm = wid & 3, wn = wid >> 2;
    const int row0 = blockIdx.y * 128, col0 = blockIdx.x * 256;
    const uint32_t sb = smem_u32(smem);

    float acc[2][8][4];
#pragma unroll
    for (int i = 0; i < 2; i++)
#pragma unroll
        for (int j = 0; j < 8; j++)
#pragma unroll
            for (int q = 0; q < 4; q++) acc[i][j][q] = 0.f;

    const int ph = lane >> 4;
    uint32_t rdA[2], rdB[4];
#pragma unroll
    for (int mf = 0; mf < 2; mf++) {
        int r = wm * 32 + mf * 16 + (lane & 15);
        rdA[mf] = sb + (uint32_t)(r * 128 + ((ph ^ (r & 7)) << 4));
    }
#pragma unroll
    for (int nf2 = 0; nf2 < 4; nf2++) {
        int r = wn * 64 + nf2 * 16 + (lane & 15);
        rdB[nf2] = sb + R_B + (uint32_t)(r * 128 + ((ph ^ (r & 7)) << 4));
    }

    const int ar  = tid >> 2;
    const int ac0 = (tid & 3) * 2;
    uint32_t wrA = sb + (uint32_t)(ar * 128 + ((ac0 ^ (ar & 7)) << 4));
    const int br  = tid >> 1;
    const int bc0 = (tid & 1) * 4;
    uint32_t wrB = sb + R_B + (uint32_t)(br * 128 + ((bc0 ^ (br & 7)) << 4));

    const char* pA = (const char*)(A + (size_t)(row0 + ar) * K + ac0 * 4);
    const char* pB = (const char*)(Bt + (size_t)(col0 + br) * K + bc0 * 4);

    auto issue = [&](int k0) {
        size_t off = (size_t)k0 * 4;
        cp16(wrA,       pA + off);
        cp16(wrA ^ 16u, pA + off + 16);
#pragma unroll
        for (int j = 0; j < 4; j++)
            cp16(wrB ^ (uint32_t)(j << 4), pB + off + j * 16);
    };

    const int nc = K >> 5;
#pragma unroll
    for (int s = 0; s < 3; s++) {
        issue(s << 5);
        cp_commit();
        wrA += STAGE; wrB += STAGE;
    }

    for (int c = 0; c < nc; c++) {
        cp_wait2();
        __syncthreads();

        if (c + 3 < nc) issue((c + 3) << 5);
        cp_commit();
        {
            const int wd = (((c + 3) & 3) == 3) ? -3 * STAGE : STAGE;
            wrA += wd; wrB += wd;
        }

#pragma unroll
        for (int ks = 0; ks < 4; ks++) {
            const uint32_t kx = (uint32_t)(ks << 5);
            uint32_t a[2][4];
            ldm4(a[0], rdA[0] ^ kx);
            ldm4(a[1], rdA[1] ^ kx);
            if (CVTA) {
#pragma unroll
                for (int mf = 0; mf < 2; mf++)
#pragma unroll
                    for (int q = 0; q < 4; q++) cvt_tf32(a[mf][q]);
            }
#pragma unroll
            for (int nf2 = 0; nf2 < 4; nf2++) {
                uint32_t t[4];
                ldm4(t, rdB[nf2] ^ kx);
#pragma unroll
                for (int mf = 0; mf < 2; mf++) {
                    mma_tf32(acc[mf][2 * nf2],     a[mf], t[0], t[2]);
                    mma_tf32(acc[mf][2 * nf2 + 1], a[mf], t[1], t[3]);
                }
            }
        }

        {
            const int rd = ((c & 3) == 3) ? -3 * STAGE : STAGE;
            rdA[0] += rd; rdA[1] += rd;
#pragma unroll
            for (int i = 0; i < 4; i++) rdB[i] += rd;
        }
    }

    // epilogue: bias + LayerNorm over 256 cols, store C
    __syncthreads();
    const int r4 = lane >> 2, c2 = (lane & 3) * 2;
    float2 bs[8];
#pragma unroll
    for (int nf = 0; nf < 8; nf++)
        bs[nf] = *(const float2*)&bias[col0 + wn * 64 + nf * 8 + c2];

    float mu[2][2], inv[2][2];
    {
        float2* part = (float2*)(smem + 4 * STAGE);  // [128][4]
#pragma unroll
        for (int mf = 0; mf < 2; mf++)
#pragma unroll
            for (int h = 0; h < 2; h++) {
                float s1 = 0.f, s2 = 0.f;
#pragma unroll
                for (int nf = 0; nf < 8; nf++) {
                    float v0 = acc[mf][nf][2 * h]     + bs[nf].x;
                    float v1 = acc[mf][nf][2 * h + 1] + bs[nf].y;
                    s1 += v0 + v1; s2 += v0 * v0 + v1 * v1;
                }
                s1 += __shfl_xor_sync(0xffffffffu, s1, 1);
                s2 += __shfl_xor_sync(0xffffffffu, s2, 1);
                s1 += __shfl_xor_sync(0xffffffffu, s1, 2);
                s2 += __shfl_xor_sync(0xffffffffu, s2, 2);
                int rt = wm * 32 + mf * 16 + h * 8 + r4;
                if ((lane & 3) == 0) part[rt * 4 + wn] = make_float2(s1, s2);
            }
        __syncthreads();
#pragma unroll
        for (int mf = 0; mf < 2; mf++)
#pragma unroll
            for (int h = 0; h < 2; h++) {
                int rt = wm * 32 + mf * 16 + h * 8 + r4;
                float s1 = 0.f, s2 = 0.f;
#pragma unroll
                for (int w = 0; w < 4; w++) {
                    float2 p = part[rt * 4 + w];
                    s1 += p.x; s2 += p.y;
                }
                float m = s1 * (1.0f / 256.0f);
                float var = s2 * (1.0f / 256.0f) - m * m;
                mu[mf][h] = m;
                inv[mf][h] = rsqrtf(var + 1e-5f);
            }
    }

#pragma unroll
    for (int mf = 0; mf < 2; mf++)
#pragma unroll
        for (int h = 0; h < 2; h++) {
            int row = row0 + wm * 32 + mf * 16 + h * 8 + r4;
#pragma unroll
            for (int nf = 0; nf < 8; nf++) {
                float v0 = (acc[mf][nf][2 * h]     + bs[nf].x - mu[mf][h]) * inv[mf][h];
                float v1 = (acc[mf][nf][2 * h + 1] + bs[nf].y - mu[mf][h]) * inv[mf][h];
                int col = col0 + wn * 64 + nf * 8 + c2;
                *(float2*)&C[(size_t)row * N + col] = make_float2(v0, v1);
            }
        }
}

// ------------- MLP GEMM: high-occupancy, 256 thr, BM=64 BN=128 ------------------
// 3 CTAs/SM (24 warps). A = g_x (pre-rounded tf32), warp tile 32x32 (acc=32),
// BK=32, 3-stage cp.async. Epilogue: bias + exact GELU + dot w2 -> atomicAdd.
__global__ __launch_bounds__(256, 3)
void gemm_mlp(const float* __restrict__ A,
              const float* __restrict__ Bt,
              const float* __restrict__ bias,
              const float* __restrict__ w2,
              float* __restrict__ logit,
              int K)
{
    extern __shared__ char smem[];
    constexpr int R_B   = 8192;              // A: 64 rows x 128B
    constexpr int STAGE = 24576;             // A 8KB + B 16KB

    const int tid = threadIdx.x, wid = tid >> 5, lane = tid & 31;
    const int wm = wid & 1, wn = wid >> 1;   // warp grid 2 (M) x 4 (N)
    const int row0 = blockIdx.y * 64, col0 = blockIdx.x * 128;
    const uint32_t sb = smem_u32(smem);

    float acc[2][4][4];
#pragma unroll
    for (int i = 0; i < 2; i++)
#pragma unroll
        for (int j = 0; j < 4; j++)
#pragma unroll
            for (int q = 0; q < 4; q++) acc[i][j][q] = 0.f;

    const int ph = lane >> 4;
    uint32_t rdA[2], rdB[2];
#pragma unroll
    for (int mf = 0; mf < 2; mf++) {
        int r = wm * 32 + mf * 16 + (lane & 15);
        rdA[mf] = sb + (uint32_t)(r * 128 + ((ph ^ (r & 7)) << 4));
    }
#pragma unroll
    for (int nf2 = 0; nf2 < 2; nf2++) {
        int r = wn * 32 + nf2 * 16 + (lane & 15);
        rdB[nf2] = sb + R_B + (uint32_t)(r * 128 + ((ph ^ (r & 7)) << 4));
    }

    // cp.async destinations: A 64 rows, 4 thr/row x 2 chunks; B 128 rows, 2 thr/row x 4
    const int ar  = tid >> 2;
    const int ac0 = (tid & 3) * 2;
    uint32_t wrA = sb + (uint32_t)(ar * 128 + ((ac0 ^ (ar & 7)) << 4));
    const int br  = tid >> 1;
    const int bc0 = (tid & 1) * 4;
    uint32_t wrB = sb + R_B + (uint32_t)(br * 128 + ((bc0 ^ (br & 7)) << 4));

    const char* pA = (const char*)(A + (size_t)(row0 + ar) * K + ac0 * 4);
    const char* pB = (const char*)(Bt + (size_t)(col0 + br) * K + bc0 * 4);

    auto issue = [&](int k0) {
        size_t off = (size_t)k0 * 4;
        cp16(wrA,       pA + off);
        cp16(wrA ^ 16u, pA + off + 16);
#pragma unroll
        for (int j = 0; j < 4; j++)
            cp16(wrB ^ (uint32_t)(j << 4), pB + off + j * 16);
    };

    const int nc = K >> 5;
    // prologue: stages 0,1
#pragma unroll
    for (int s = 0; s < 2; s++) {
        issue(s << 5);
        cp_commit();
        wrA += STAGE; wrB += STAGE;          // now at stage 2
    }

    for (int c = 0; c < nc; c++) {
        cp_wait1();          // chunk c complete
        __syncthreads();

        if (c + 2 < nc) issue((c + 2) << 5);
        cp_commit();
        {   // write stage (c+2)%3 -> (c+3)%3
            const int wd = (((c + 2) % 3) == 2) ? -2 * STAGE : STAGE;
            wrA += wd; wrB += wd;
        }

#pragma unroll
        for (int ks = 0; ks < 4; ks++) {
            const uint32_t kx = (uint32_t)(ks << 5);
            uint32_t a[2][4];
            ldm4(a[0], rdA[0] ^ kx);
            ldm4(a[1], rdA[1] ^ kx);
#pragma unroll
            for (int nf2 = 0; nf2 < 2; nf2++) {
                uint32_t t[4];
                ldm4(t, rdB[nf2] ^ kx);
#pragma unroll
                for (int mf = 0; mf < 2; mf++) {
                    mma_tf32(acc[mf][2 * nf2],     a[mf], t[0], t[2]);
                    mma_tf32(acc[mf][2 * nf2 + 1], a[mf], t[1], t[3]);
                }
            }
        }

        {   // read stage c%3 -> (c+1)%3
            const int rd = ((c % 3) == 2) ? -2 * STAGE : STAGE;
            rdA[0] += rd; rdA[1] += rd;
            rdB[0] += rd; rdB[1] += rd;
        }
    }

    // epilogue: bias + GELU + dot(w2) -> atomicAdd logit[row]
    __syncthreads();
    const int r4 = lane >> 2, c2 = (lane & 3) * 2;
    float2 bs[4], ws[4];
#pragma unroll
    for (int nf = 0; nf < 4; nf++) {
        bs[nf] = *(const float2*)&bias[col0 + wn * 32 + nf * 8 + c2];
        ws[nf] = *(const float2*)&w2[col0 + wn * 32 + nf * 8 + c2];
    }
#pragma unroll
    for (int mf = 0; mf < 2; mf++)
#pragma unroll
        for (int h = 0; h < 2; h++) {
            float s = 0.f;
#pragma unroll
            for (int nf = 0; nf < 4; nf++) {
                float v0 = acc[mf][nf][2 * h]     + bs[nf].x;
                float v1 = acc[mf][nf][2 * h + 1] + bs[nf].y;
                v0 = 0.5f * v0 * (1.0f + erff(v0 * 0.70710678118654752f));
                v1 = 0.5f * v1 * (1.0f + erff(v1 * 0.70710678118654752f));
                s += v0 * ws[nf].x + v1 * ws[nf].y;
            }
            s += __shfl_xor_sync(0xffffffffu, s, 1);
            s += __shfl_xor_sync(0xffffffffu, s, 2);
            if ((lane & 3) == 0) {
                int row = row0 + wm * 32 + mf * 16 + h * 8 + r4;
                atomicAdd(&logit[row], s);
            }
        }
}

// -------- fused fractional shift + causal window context: g_actx from g_a -------
__global__ void ctx_kernel(const float* __restrict__ theta)
{
    const int t = blockIdx.x;
    const int b = blockIdx.y;
    const int d = threadIdx.x;

    float th    = fminf(fmaxf(theta[0], -12.f), 12.f);
    float delta = 2.0f + 4.0f / (1.0f + expf(-th));
    float dl    = fminf(fmaxf(delta, 0.f), (float)(T_ - 1));
    float nf    = floorf(dl);
    float alpha = dl - nf;
    int   ni    = (int)nf;

    float center = fminf(fmaxf((float)t + delta, 0.f), (float)t);
    int lo = max(0, (int)floorf(center - 5.0f) - 1);
    int hi = min(t, (int)ceilf (center + 5.0f) + 1);

    const float* ab = g_a + (size_t)b * T_ * DM_;
    float sum = 0.f; int cnt = 0;
    for (int tau = lo; tau <= hi; tau++) {
        if (fabsf((float)tau - center) <= 5.0f) {
            cnt++;
            int i0 = min(max(tau - ni, 0), T_ - 1);
            int i1 = min(i0 + 1, T_ - 1);
            sum += (1.0f - alpha) * ab[i0 * DM_ + d] + alpha * ab[i1 * DM_ + d];
        }
    }
    g_actx[((size_t)b * T_ + t) * DM_ + d] = sum / fmaxf((float)cnt, 1e-8f);
}

// -- build X = [an, vn, an*vn] tf32-rounded, with L2 normalization (warp/row) ----
__global__ void buildx_kernel()
{
    const int row  = blockIdx.x * 8 + (threadIdx.x >> 5);
    const int lane = threadIdx.x & 31;
    const float* v  = g_v    + (size_t)row * DM_;
    const float* ac = g_actx + (size_t)row * DM_;

    float vv[8], aa[8];
    float sv = 0.f, sa = 0.f;
#pragma unroll
    for (int i = 0; i < 8; i++) {
        vv[i] = v[lane + 32 * i];
        aa[i] = ac[lane + 32 * i];
        sv += vv[i] * vv[i];
        sa += aa[i] * aa[i];
    }
#pragma unroll
    for (int o = 16; o > 0; o >>= 1) {
        sv += __shfl_xor_sync(0xffffffffu, sv, o);
        sa += __shfl_xor_sync(0xffffffffu, sa, o);
    }
    float iv = 1.0f / fmaxf(sqrtf(sv), 1e-8f);
    float ia = 1.0f / fmaxf(sqrtf(sa), 1e-8f);

    float* x = g_x + (size_t)row * (3 * DM_);
#pragma unroll
    for (int i = 0; i < 8; i++) {
        int d = lane + 32 * i;
        float an = aa[i] * ia, vn = vv[i] * iv;
        x[d]           = round_tf32(an);
        x[DM_ + d]     = round_tf32(vn);
        x[2 * DM_ + d] = round_tf32(an * vn);
    }
}

// -------- gate: logit -> sigmoid -> blend: out = g*a_ctx + (1-g)*v --------------
__global__ void gate_kernel(const float* __restrict__ b2, float* __restrict__ out)
{
    const int row = blockIdx.x;
    const int tid = threadIdx.x;
    float logitv = fminf(fmaxf(g_logit[row] + b2[0], -12.f), 12.f);
    float g = 1.0f / (1.0f + expf(-logitv));
    g = fminf(fmaxf(g, 0.05f), 0.95f);
    float ac = g_actx[(size_t)row * DM_ + tid];
    float v  = g_v  [(size_t)row * DM_ + tid];
    out[(size_t)row * DM_ + tid] = g * ac + (1.0f - g) * v;
}

// --------------------------------- launcher ------------------------------------
extern "C" void kernel_launch(void* const* d_in, const int* in_sizes, int n_in,
                              void* d_out, int out_size)
{
    const float* video = (const float*)d_in[0];
    const float* audio = (const float*)d_in[1];
    const float* Wv    = (const float*)d_in[2];
    const float* bv    = (const float*)d_in[3];
    const float* Wa    = (const float*)d_in[4];
    const float* ba    = (const float*)d_in[5];
    const float* theta = (const float*)d_in[6];
    const float* W1    = (const float*)d_in[7];
    const float* b1    = (const float*)d_in[8];
    const float* W2    = (const float*)d_in[9];
    const float* b2    = (const float*)d_in[10];
    float* out = (float*)d_out;

    float *pv, *pa, *px, *plog, *wvt, *wat, *w1t;
    cudaGetSymbolAddress((void**)&pv,   g_v);
    cudaGetSymbolAddress((void**)&pa,   g_a);
    cudaGetSymbolAddress((void**)&px,   g_x);
    cudaGetSymbolAddress((void**)&plog, g_logit);
    cudaGetSymbolAddress((void**)&wvt,  g_wvt);
    cudaGetSymbolAddress((void**)&wat,  g_wat);
    cudaGetSymbolAddress((void**)&w1t,  g_w1t);

    const int SMEM_LN  = 4 * 49152 + 128 * 4 * 8;   // 200704
    const int SMEM_MLP = 3 * 24576;                 // 73728
    cudaFuncSetAttribute((const void*)gemm_mma<2, 1>,
                         cudaFuncAttributeMaxDynamicSharedMemorySize, SMEM_LN);
    cudaFuncSetAttribute((const void*)gemm_mlp,
                         cudaFuncAttributeMaxDynamicSharedMemorySize, SMEM_MLP);

    cudaMemsetAsync(plog, 0, ROWS * sizeof(float));

    dim3 wblk(32, 8);
    wprep_kernel<<<dim3(DM_  / 32, 1024 / 32), wblk>>>(Wv, wvt, 1024, DM_);
    wprep_kernel<<<dim3(DM_  / 32,  768 / 32), wblk>>>(Wa, wat,  768, DM_);
    wprep_kernel<<<dim3(HID_ / 32,  768 / 32), wblk>>>(W1, w1t,  768, HID_);

    // v = LN(video @ Wv + bv)   M=16384 K=1024 N=256
    gemm_mma<2, 1><<<dim3(1, ROWS / 128), dim3(512), SMEM_LN>>>(video, wvt, bv, pv,
                                                                DM_, 1024);
    // a = LN(audio @ Wa + ba)   M=16384 K=768  N=256
    gemm_mma<2, 1><<<dim3(1, ROWS / 128), dim3(512), SMEM_LN>>>(audio, wat, ba, pa,
                                                                DM_, 768);
    // a_ctx
    ctx_kernel<<<dim3(T_, B_), dim3(256)>>>(theta);
    // X = [an, vn, an*vn] (tf32-rounded)
    buildx_kernel<<<ROWS / 8, dim3(256)>>>();
    // logits += gelu(X @ W1 + b1) . W2   (high-occupancy MLP kernel)
    gemm_mlp<<<dim3(HID_ / 128, ROWS / 64), dim3(256), SMEM_MLP>>>(px, w1t, b1,
                                                                   W2, plog, 768);
    // gate + blend
    gate_kernel<<<ROWS, dim3(256)>>>(b2, out);
}